// round 1
// baseline (speedup 1.0000x reference)
#include <cuda_runtime.h>
#include <cstdint>

// Problem dims (fixed by the reference)
#define BB   4
#define SS   1024
#define DD   1024
#define HH   16
#define DK   64
#define DFF  4096
#define ROWS (BB * SS)          // 4096
#define BHH  (BB * HH)          // 64

// ---------------- scratch (static device globals; no allocation) ----------------
__device__ float g_xn [ (size_t)ROWS * DD ];
__device__ float g_q  [ (size_t)ROWS * DD ];
__device__ float g_k  [ (size_t)ROWS * DD ];
__device__ float g_v  [ (size_t)ROWS * DD ];
__device__ float g_ctx[ (size_t)ROWS * DD ];
__device__ float g_x1 [ (size_t)ROWS * DD ];
__device__ float g_ff [ (size_t)ROWS * DFF ];
__device__ float g_scores[ (size_t)BHH * SS * SS ];   // 256 MiB

// ---------------- LayerNorm (torch-style: ddof=1, eps on std, scalar a/b) -------
__global__ __launch_bounds__(256) void ln_kernel(const float* __restrict__ x,
                                                 float* __restrict__ y,
                                                 const float* __restrict__ alpha,
                                                 const float* __restrict__ beta)
{
    __shared__ float red[256];
    const int row = blockIdx.x;
    const int tid = threadIdx.x;
    const float* xr = x + (size_t)row * DD;
    float* yr = y + (size_t)row * DD;

    float s = 0.f;
    #pragma unroll
    for (int i = tid; i < DD; i += 256) s += xr[i];
    red[tid] = s; __syncthreads();
    for (int off = 128; off > 0; off >>= 1) {
        if (tid < off) red[tid] += red[tid + off];
        __syncthreads();
    }
    const float mean = red[0] * (1.0f / DD);
    __syncthreads();

    float v = 0.f;
    #pragma unroll
    for (int i = tid; i < DD; i += 256) { float d = xr[i] - mean; v += d * d; }
    red[tid] = v; __syncthreads();
    for (int off = 128; off > 0; off >>= 1) {
        if (tid < off) red[tid] += red[tid + off];
        __syncthreads();
    }
    const float stdv = sqrtf(red[0] / (float)(DD - 1));   // ddof = 1
    const float a = alpha[0], b = beta[0];
    const float inv = a / (stdv + 1e-6f);                  // eps added to std

    #pragma unroll
    for (int i = tid; i < DD; i += 256) yr[i] = (xr[i] - mean) * inv + b;
}

// ---------------- generic SGEMM: C = A[MxK] * B[KxN] + bias (+relu)(+res) -------
#define BM 128
#define BN 128
#define BK 8
#define TM 8
#define TN 8

__global__ __launch_bounds__(256) void sgemm_kernel(
    const float* __restrict__ A, const float* __restrict__ B,
    const float* __restrict__ bias, const float* __restrict__ res,
    float* __restrict__ C, int M, int N, int K, int doRelu)
{
    __shared__ float As[BK][BM];
    __shared__ float Bs[BK][BN];

    const int tid  = threadIdx.x;
    const int cRow = blockIdx.y;   // M tile
    const int cCol = blockIdx.x;   // N tile

    const float* Ab = A + (size_t)cRow * BM * K;
    const float* Bb = B + (size_t)cCol * BN;

    float acc[TM][TN];
    #pragma unroll
    for (int i = 0; i < TM; i++)
        #pragma unroll
        for (int j = 0; j < TN; j++) acc[i][j] = 0.f;

    const int aRow = tid >> 1;            // 0..127
    const int aCol = (tid & 1) * 4;       // 0 or 4
    const int bRow = tid >> 5;            // 0..7
    const int bCol = (tid & 31) * 4;      // 0..124

    const int tr = (tid >> 4) * TM;       // 0..120
    const int tc = (tid & 15) * TN;       // 0..120

    for (int k0 = 0; k0 < K; k0 += BK) {
        float4 av = *reinterpret_cast<const float4*>(Ab + (size_t)aRow * K + k0 + aCol);
        As[aCol + 0][aRow] = av.x;
        As[aCol + 1][aRow] = av.y;
        As[aCol + 2][aRow] = av.z;
        As[aCol + 3][aRow] = av.w;
        float4 bv = *reinterpret_cast<const float4*>(Bb + (size_t)(k0 + bRow) * N + bCol);
        *reinterpret_cast<float4*>(&Bs[bRow][bCol]) = bv;
        __syncthreads();

        #pragma unroll
        for (int k = 0; k < BK; k++) {
            float ra[TM], rb[TN];
            #pragma unroll
            for (int i = 0; i < TM; i++) ra[i] = As[k][tr + i];
            #pragma unroll
            for (int j = 0; j < TN; j++) rb[j] = Bs[k][tc + j];
            #pragma unroll
            for (int i = 0; i < TM; i++)
                #pragma unroll
                for (int j = 0; j < TN; j++)
                    acc[i][j] = fmaf(ra[i], rb[j], acc[i][j]);
        }
        __syncthreads();
    }

    const int gr = cRow * BM + tr;
    const int gc = cCol * BN + tc;
    #pragma unroll
    for (int i = 0; i < TM; i++) {
        #pragma unroll
        for (int j = 0; j < TN; j++) {
            float c = acc[i][j] + bias[gc + j];
            if (doRelu) c = fmaxf(c, 0.f);
            if (res) c += res[(size_t)(gr + i) * N + gc + j];
            C[(size_t)(gr + i) * N + gc + j] = c;
        }
    }
}

// ---------------- attention scores: S[bh,i,j] = (q_i . k_j) / 8, masked ---------
__global__ __launch_bounds__(256) void scores_kernel(
    const float* __restrict__ q, const float* __restrict__ k,
    const int* __restrict__ mask, float* __restrict__ scores)
{
    __shared__ float Qs[64][68];
    __shared__ float Ks[64][68];

    const int tid   = threadIdx.x;
    const int kBase = blockIdx.x * 64;
    const int qBase = blockIdx.y * 64;
    const int bh    = blockIdx.z;
    const int b = bh / HH, h = bh % HH;
    const int colOff = h * DK;

    // load 64x64 tiles (float4, 4 rows/pass)
    const int lr = tid >> 4;          // 0..15
    const int lc = (tid & 15) * 4;    // 0..60
    #pragma unroll
    for (int p = 0; p < 4; p++) {
        const int row = p * 16 + lr;
        float4 qv = *reinterpret_cast<const float4*>(
            q + (size_t)(b * SS + qBase + row) * DD + colOff + lc);
        Qs[row][lc] = qv.x; Qs[row][lc+1] = qv.y; Qs[row][lc+2] = qv.z; Qs[row][lc+3] = qv.w;
        float4 kv = *reinterpret_cast<const float4*>(
            k + (size_t)(b * SS + kBase + row) * DD + colOff + lc);
        Ks[row][lc] = kv.x; Ks[row][lc+1] = kv.y; Ks[row][lc+2] = kv.z; Ks[row][lc+3] = kv.w;
    }
    __syncthreads();

    const int ty = tid >> 4, tx = tid & 15;
    float acc[4][4];
    #pragma unroll
    for (int i = 0; i < 4; i++)
        #pragma unroll
        for (int j = 0; j < 4; j++) acc[i][j] = 0.f;

    #pragma unroll 8
    for (int d = 0; d < DK; d++) {
        float ra[4], rb[4];
        #pragma unroll
        for (int i = 0; i < 4; i++) ra[i] = Qs[ty * 4 + i][d];
        #pragma unroll
        for (int j = 0; j < 4; j++) rb[j] = Ks[tx * 4 + j][d];
        #pragma unroll
        for (int i = 0; i < 4; i++)
            #pragma unroll
            for (int j = 0; j < 4; j++)
                acc[i][j] = fmaf(ra[i], rb[j], acc[i][j]);
    }

    #pragma unroll
    for (int i = 0; i < 4; i++) {
        const int gi = qBase + ty * 4 + i;
        #pragma unroll
        for (int j = 0; j < 4; j++) {
            const int gj = kBase + tx * 4 + j;
            float s = acc[i][j] * 0.125f;                 // 1/sqrt(64)
            if (mask[b * SS + gj] == 0) s = -1e9f;
            scores[((size_t)bh * SS + gi) * SS + gj] = s;
        }
    }
}

// ---------------- row softmax in place (rows of length 1024) --------------------
__global__ __launch_bounds__(256) void softmax_kernel(float* __restrict__ scores)
{
    __shared__ float red[256];
    float* row = scores + (size_t)blockIdx.x * SS;
    const int tid = threadIdx.x;

    float m = -3.4e38f;
    #pragma unroll
    for (int i = tid; i < SS; i += 256) m = fmaxf(m, row[i]);
    red[tid] = m; __syncthreads();
    for (int off = 128; off > 0; off >>= 1) {
        if (tid < off) red[tid] = fmaxf(red[tid], red[tid + off]);
        __syncthreads();
    }
    const float mx = red[0]; __syncthreads();

    float s = 0.f;
    float vals[4];
    #pragma unroll
    for (int p = 0; p < 4; p++) {
        vals[p] = expf(row[tid + p * 256] - mx);
        s += vals[p];
    }
    red[tid] = s; __syncthreads();
    for (int off = 128; off > 0; off >>= 1) {
        if (tid < off) red[tid] += red[tid + off];
        __syncthreads();
    }
    const float inv = 1.0f / red[0];
    #pragma unroll
    for (int p = 0; p < 4; p++) row[tid + p * 256] = vals[p] * inv;
}

// ---------------- ctx = attn @ V  (per head, M=S, N=64, K=S) --------------------
__global__ __launch_bounds__(256) void ctx_kernel(
    const float* __restrict__ attn, const float* __restrict__ v,
    float* __restrict__ ctx)
{
    __shared__ float As[64][68];
    __shared__ float Vs[64][68];

    const int tid   = threadIdx.x;
    const int qBase = blockIdx.x * 64;
    const int bh    = blockIdx.y;
    const int b = bh / HH, h = bh % HH;
    const int colOff = h * DK;

    const int lr = tid >> 4;
    const int lc = (tid & 15) * 4;
    const int ty = tid >> 4, tx = tid & 15;

    float acc[4][4];
    #pragma unroll
    for (int i = 0; i < 4; i++)
        #pragma unroll
        for (int j = 0; j < 4; j++) acc[i][j] = 0.f;

    for (int jBase = 0; jBase < SS; jBase += 64) {
        #pragma unroll
        for (int p = 0; p < 4; p++) {
            const int row = p * 16 + lr;
            float4 av = *reinterpret_cast<const float4*>(
                attn + ((size_t)bh * SS + qBase + row) * SS + jBase + lc);
            As[row][lc] = av.x; As[row][lc+1] = av.y; As[row][lc+2] = av.z; As[row][lc+3] = av.w;
            float4 vv = *reinterpret_cast<const float4*>(
                v + (size_t)(b * SS + jBase + row) * DD + colOff + lc);
            Vs[row][lc] = vv.x; Vs[row][lc+1] = vv.y; Vs[row][lc+2] = vv.z; Vs[row][lc+3] = vv.w;
        }
        __syncthreads();

        #pragma unroll 8
        for (int jj = 0; jj < 64; jj++) {
            float ra[4], rb[4];
            #pragma unroll
            for (int i = 0; i < 4; i++) ra[i] = As[ty * 4 + i][jj];
            #pragma unroll
            for (int j = 0; j < 4; j++) rb[j] = Vs[jj][tx * 4 + j];
            #pragma unroll
            for (int i = 0; i < 4; i++)
                #pragma unroll
                for (int j = 0; j < 4; j++)
                    acc[i][j] = fmaf(ra[i], rb[j], acc[i][j]);
        }
        __syncthreads();
    }

    #pragma unroll
    for (int i = 0; i < 4; i++)
        #pragma unroll
        for (int j = 0; j < 4; j++)
            ctx[(size_t)(b * SS + qBase + ty * 4 + i) * DD + colOff + tx * 4 + j] = acc[i][j];
}

// ---------------- launch ---------------------------------------------------------
extern "C" void kernel_launch(void* const* d_in, const int* in_sizes, int n_in,
                              void* d_out, int out_size)
{
    const float* x      = (const float*)d_in[0];
    const int*   mask   = (const int*)  d_in[1];
    const float* wq     = (const float*)d_in[2];
    const float* bq     = (const float*)d_in[3];
    const float* wk     = (const float*)d_in[4];
    const float* bk     = (const float*)d_in[5];
    const float* wv     = (const float*)d_in[6];
    const float* bv     = (const float*)d_in[7];
    const float* wo     = (const float*)d_in[8];
    const float* bo     = (const float*)d_in[9];
    const float* w1     = (const float*)d_in[10];
    const float* b1     = (const float*)d_in[11];
    const float* w2     = (const float*)d_in[12];
    const float* b2     = (const float*)d_in[13];
    const float* alpha1 = (const float*)d_in[14];
    const float* beta1  = (const float*)d_in[15];
    const float* alpha2 = (const float*)d_in[16];
    const float* beta2  = (const float*)d_in[17];
    float* out = (float*)d_out;

    float *xn, *q, *k, *v, *ctx, *x1, *ff, *scores;
    cudaGetSymbolAddress((void**)&xn,     g_xn);
    cudaGetSymbolAddress((void**)&q,      g_q);
    cudaGetSymbolAddress((void**)&k,      g_k);
    cudaGetSymbolAddress((void**)&v,      g_v);
    cudaGetSymbolAddress((void**)&ctx,    g_ctx);
    cudaGetSymbolAddress((void**)&x1,     g_x1);
    cudaGetSymbolAddress((void**)&ff,     g_ff);
    cudaGetSymbolAddress((void**)&scores, g_scores);

    // 1) LN1
    ln_kernel<<<ROWS, 256>>>(x, xn, alpha1, beta1);

    // 2) Q, K, V projections
    dim3 gProj(DD / BN, ROWS / BM);          // (8, 32)
    sgemm_kernel<<<gProj, 256>>>(xn, wq, bq, nullptr, q, ROWS, DD, DD, 0);
    sgemm_kernel<<<gProj, 256>>>(xn, wk, bk, nullptr, k, ROWS, DD, DD, 0);
    sgemm_kernel<<<gProj, 256>>>(xn, wv, bv, nullptr, v, ROWS, DD, DD, 0);

    // 3) attention
    scores_kernel<<<dim3(SS / 64, SS / 64, BHH), 256>>>(q, k, mask, scores);
    softmax_kernel<<<BHH * SS, 256>>>(scores);
    ctx_kernel<<<dim3(SS / 64, BHH), 256>>>(scores, v, ctx);

    // 4) output projection + residual
    sgemm_kernel<<<gProj, 256>>>(ctx, wo, bo, x, x1, ROWS, DD, DD, 0);

    // 5) LN2 + FFN + residual
    ln_kernel<<<ROWS, 256>>>(x1, xn, alpha2, beta2);
    dim3 gFF1(DFF / BN, ROWS / BM);          // (32, 32)
    sgemm_kernel<<<gFF1, 256>>>(xn, w1, b1, nullptr, ff, ROWS, DFF, DD, 1);
    sgemm_kernel<<<gProj, 256>>>(ff, w2, b2, x1, out, ROWS, DD, DFF, 0);
}

// round 3
// speedup vs baseline: 3.0792x; 3.0792x over previous
#include <cuda_runtime.h>
#include <cstdint>

// ---------------- problem dims ----------------
#define BBX   4
#define SSZ   1024
#define DDM   1024
#define HHX   16
#define DFF   4096
#define ROWS  4096          // BBX*SSZ
#define BHH   64            // BBX*HHX
#define QKVLD 3072
#define SA    20            // padded smem stride (floats)

// ---------------- scratch (static device globals) ----------------
__device__ float g_xn   [(size_t)ROWS * DDM];
__device__ float g_qkv  [(size_t)ROWS * QKVLD];
__device__ float g_vt   [(size_t)BHH * 64 * SSZ];
__device__ float g_ctx  [(size_t)ROWS * DDM];
__device__ float g_x1   [(size_t)ROWS * DDM];
__device__ float g_ff   [(size_t)ROWS * DFF];
__device__ float g_sc   [(size_t)BHH * SSZ * SSZ];
__device__ float g_wqkvt[(size_t)QKVLD * DDM];
__device__ float g_wot  [(size_t)DDM * DDM];
__device__ float g_w1t  [(size_t)DFF * DDM];
__device__ float g_w2t  [(size_t)DDM * DFF];
__device__ float g_bqkv [QKVLD];

// ---------------- helpers ----------------
__device__ __forceinline__ uint32_t smem_u32(const void* p) {
    uint32_t a;
    asm("{ .reg .u64 t; cvta.to.shared.u64 t, %1; cvt.u32.u64 %0, t; }"
        : "=r"(a) : "l"(p));
    return a;
}
__device__ __forceinline__ float tf32r(float x) {   // RNE round to tf32
    float y;
    asm("cvt.rna.tf32.f32 %0, %1;" : "=f"(y) : "f"(x));
    return y;
}
__device__ __forceinline__ void cpasync16(uint32_t s, const void* g) {
    asm volatile("cp.async.cg.shared.global [%0], [%1], 16;" :: "r"(s), "l"(g));
}
#define CP_COMMIT() asm volatile("cp.async.commit_group;" ::: "memory")
#define CP_WAIT1()  asm volatile("cp.async.wait_group 1;" ::: "memory")

__device__ __forceinline__ void mma_tf32(float (&d)[4],
                                         const uint32_t (&a)[4],
                                         const uint32_t (&b)[2]) {
    asm volatile(
        "mma.sync.aligned.m16n8k8.row.col.f32.tf32.tf32.f32 "
        "{%0,%1,%2,%3},{%4,%5,%6,%7},{%8,%9},{%0,%1,%2,%3};"
        : "+f"(d[0]), "+f"(d[1]), "+f"(d[2]), "+f"(d[3])
        : "r"(a[0]), "r"(a[1]), "r"(a[2]), "r"(a[3]),
          "r"(b[0]), "r"(b[1]));
}

// ---------------- cp.async tile loader (one BK=16 chunk) ----------------
template <int NI>
__device__ __forceinline__ void load_chunk(const float* __restrict__ A, int lda,
                                           const float* __restrict__ B, int ldb,
                                           int k0, uint32_t sA, uint32_t sB, int tid)
{
    constexpr int BN = NI * 32;
    #pragma unroll
    for (int it = 0; it < 2; it++) {
        const int idx = tid + it * 256;
        const int r = idx >> 2, c = idx & 3;
        cpasync16(sA + (uint32_t)(r * SA + c * 4) * 4,
                  A + (size_t)r * lda + k0 + c * 4);
    }
    #pragma unroll
    for (int it = 0; it < (BN * 4) / 256; it++) {
        const int idx = tid + it * 256;
        const int n = idx >> 2, c = idx & 3;
        cpasync16(sB + (uint32_t)(n * SA + c * 4) * 4,
                  B + (size_t)n * ldb + k0 + c * 4);
    }
}

// ---------------- mma.sync tf32 mainloop -------------------------------
// block tile 128 x (NI*32); 8 warps (2 m-warps x 4 n-warps), warp tile 64x(NI*8)
template <int NI>
__device__ __forceinline__ void mma_mainloop(const float* __restrict__ A, int lda,
                                             const float* __restrict__ B, int ldb,
                                             int K, float (&acc)[4][NI][4], char* dyn)
{
    constexpr int ASZ = 128 * SA * 4;
    constexpr int BSZ = NI * 32 * SA * 4;
    constexpr int STG = ASZ + BSZ;
    const int tid = threadIdx.x;
    const int wid = tid >> 5, lane = tid & 31;
    const int wm = wid >> 2, wn = wid & 3;
    const int gid = lane >> 2, tig = lane & 3;
    const uint32_t sbase = smem_u32(dyn);

    const int nk = K >> 4;
    #pragma unroll
    for (int s = 0; s < 2; s++) {
        if (s < nk)
            load_chunk<NI>(A, lda, B, ldb, s * 16,
                           sbase + s * STG, sbase + s * STG + ASZ, tid);
        CP_COMMIT();
    }

    for (int c = 0; c < nk; c++) {
        CP_WAIT1();
        __syncthreads();
        const int nst = c + 2;
        if (nst < nk) {
            const int s2 = nst % 3;
            load_chunk<NI>(A, lda, B, ldb, nst * 16,
                           sbase + s2 * STG, sbase + s2 * STG + ASZ, tid);
        }
        CP_COMMIT();

        const int s = c % 3;
        const float* As = (const float*)(dyn + s * STG);
        const float* Bs = (const float*)(dyn + s * STG + ASZ);

        #pragma unroll
        for (int kk = 0; kk < 2; kk++) {
            const int kofs = kk * 8;
            uint32_t afr[4][4];
            #pragma unroll
            for (int mi = 0; mi < 4; mi++) {
                const float* ar = As + (wm * 64 + mi * 16 + gid) * SA + kofs + tig;
                afr[mi][0] = __float_as_uint(ar[0]);
                afr[mi][1] = __float_as_uint(ar[8 * SA]);
                afr[mi][2] = __float_as_uint(ar[4]);
                afr[mi][3] = __float_as_uint(ar[8 * SA + 4]);
            }
            uint32_t bfr[NI][2];
            #pragma unroll
            for (int ni = 0; ni < NI; ni++) {
                const float* br = Bs + (wn * NI * 8 + ni * 8 + gid) * SA + kofs + tig;
                bfr[ni][0] = __float_as_uint(br[0]);
                bfr[ni][1] = __float_as_uint(br[4]);
            }
            #pragma unroll
            for (int mi = 0; mi < 4; mi++)
                #pragma unroll
                for (int ni = 0; ni < NI; ni++)
                    mma_tf32(acc[mi][ni], afr[mi], bfr[ni]);
        }
    }
}

// ---------------- dense GEMM: C = A[M,K] . Bt[N,K]^T + bias (+relu)(+res)(+round)
__global__ __launch_bounds__(256, 2) void gemm_mma_kernel(
    const float* __restrict__ A, int lda,
    const float* __restrict__ Bt,
    const float* __restrict__ bias, const float* __restrict__ res,
    float* __restrict__ C, int ldc, int K, int doRelu, int doRound)
{
    extern __shared__ char dyn[];
    const int mBase = blockIdx.y * 128;
    const int nBase = blockIdx.x * 128;
    const float* Ab = A + (size_t)mBase * lda;
    const float* Bb = Bt + (size_t)nBase * K;

    float acc[4][4][4];
    #pragma unroll
    for (int i = 0; i < 4; i++)
        #pragma unroll
        for (int j = 0; j < 4; j++)
            #pragma unroll
            for (int q = 0; q < 4; q++) acc[i][j][q] = 0.f;

    mma_mainloop<4>(Ab, lda, Bb, K, K, acc, dyn);

    const int wid = threadIdx.x >> 5, lane = threadIdx.x & 31;
    const int wm = wid >> 2, wn = wid & 3;
    const int gid = lane >> 2, tig = lane & 3;
    const int mW = mBase + wm * 64;
    const int nW = nBase + wn * 32;

    #pragma unroll
    for (int mi = 0; mi < 4; mi++) {
        #pragma unroll
        for (int half = 0; half < 2; half++) {
            const int row = mW + mi * 16 + gid + half * 8;
            float* cRow = C + (size_t)row * ldc;
            const float* rRow = res ? res + (size_t)row * ldc : nullptr;
            #pragma unroll
            for (int ni = 0; ni < 4; ni++) {
                const int col = nW + ni * 8 + tig * 2;
                float v0 = acc[mi][ni][half * 2 + 0] + bias[col];
                float v1 = acc[mi][ni][half * 2 + 1] + bias[col + 1];
                if (doRelu) { v0 = fmaxf(v0, 0.f); v1 = fmaxf(v1, 0.f); }
                if (rRow)   { v0 += rRow[col];      v1 += rRow[col + 1]; }
                if (doRound){ v0 = tf32r(v0);       v1 = tf32r(v1); }
                *reinterpret_cast<float2*>(cRow + col) = make_float2(v0, v1);
            }
        }
    }
}

// ---------------- scores: S[bh,m,n] = (q_m.k_n)/8, masked ----------------
__global__ __launch_bounds__(256, 2) void scores_mma_kernel(
    const float* __restrict__ qkv, const int* __restrict__ mask,
    float* __restrict__ sc)
{
    extern __shared__ char dyn[];
    const int bh = blockIdx.z, b = bh >> 4, h = bh & 15;
    const int mBase = blockIdx.y * 128;
    const int nBase = blockIdx.x * 128;
    const float* Ab = qkv + ((size_t)(b * SSZ + mBase)) * QKVLD + h * 64;          // q
    const float* Bb = qkv + ((size_t)(b * SSZ + nBase)) * QKVLD + 1024 + h * 64;   // k

    float acc[4][4][4];
    #pragma unroll
    for (int i = 0; i < 4; i++)
        #pragma unroll
        for (int j = 0; j < 4; j++)
            #pragma unroll
            for (int q = 0; q < 4; q++) acc[i][j][q] = 0.f;

    mma_mainloop<4>(Ab, QKVLD, Bb, QKVLD, 64, acc, dyn);

    const int wid = threadIdx.x >> 5, lane = threadIdx.x & 31;
    const int wm = wid >> 2, wn = wid & 3;
    const int gid = lane >> 2, tig = lane & 3;
    const int mW = mBase + wm * 64;
    const int nW = nBase + wn * 32;
    const int* mrow = mask + b * SSZ;

    #pragma unroll
    for (int mi = 0; mi < 4; mi++) {
        #pragma unroll
        for (int half = 0; half < 2; half++) {
            const int row = mW + mi * 16 + gid + half * 8;
            float* cRow = sc + ((size_t)bh * SSZ + row) * SSZ;
            #pragma unroll
            for (int ni = 0; ni < 4; ni++) {
                const int col = nW + ni * 8 + tig * 2;
                float v0 = acc[mi][ni][half * 2 + 0] * 0.125f;
                float v1 = acc[mi][ni][half * 2 + 1] * 0.125f;
                if (mrow[col] == 0)     v0 = -1e9f;
                if (mrow[col + 1] == 0) v1 = -1e9f;
                *reinterpret_cast<float2*>(cRow + col) = make_float2(v0, v1);
            }
        }
    }
}

// ---------------- ctx: ctx[b*S+m, h*64+n] = attn[bh,m,:].vt[bh,n,:] ------
__global__ __launch_bounds__(256, 2) void ctx_mma_kernel(
    const float* __restrict__ attn, const float* __restrict__ vt,
    float* __restrict__ ctx)
{
    extern __shared__ char dyn[];
    const int bh = blockIdx.z, b = bh >> 4, h = bh & 15;
    const int mBase = blockIdx.y * 128;
    const float* Ab = attn + ((size_t)bh * SSZ + mBase) * SSZ;
    const float* Bb = vt + (size_t)bh * 64 * SSZ;

    float acc[4][2][4];
    #pragma unroll
    for (int i = 0; i < 4; i++)
        #pragma unroll
        for (int j = 0; j < 2; j++)
            #pragma unroll
            for (int q = 0; q < 4; q++) acc[i][j][q] = 0.f;

    mma_mainloop<2>(Ab, SSZ, Bb, SSZ, SSZ, acc, dyn);

    const int wid = threadIdx.x >> 5, lane = threadIdx.x & 31;
    const int wm = wid >> 2, wn = wid & 3;
    const int gid = lane >> 2, tig = lane & 3;
    const int mW = mBase + wm * 64;
    const int nW = wn * 16;

    #pragma unroll
    for (int mi = 0; mi < 4; mi++) {
        #pragma unroll
        for (int half = 0; half < 2; half++) {
            const int row = mW + mi * 16 + gid + half * 8;
            float* oRow = ctx + (size_t)(b * SSZ + row) * DDM + h * 64;
            #pragma unroll
            for (int ni = 0; ni < 2; ni++) {
                const int col = nW + ni * 8 + tig * 2;
                float v0 = tf32r(acc[mi][ni][half * 2 + 0]);
                float v1 = tf32r(acc[mi][ni][half * 2 + 1]);
                *reinterpret_cast<float2*>(oRow + col) = make_float2(v0, v1);
            }
        }
    }
}

// ---------------- LayerNorm (ddof=1, eps on std, scalar a/b), tf32 out ---
__global__ __launch_bounds__(256) void ln_kernel(const float* __restrict__ x,
                                                 float* __restrict__ y,
                                                 const float* __restrict__ alpha,
                                                 const float* __restrict__ beta)
{
    __shared__ float red[256];
    const int row = blockIdx.x, tid = threadIdx.x;
    const float* xr = x + (size_t)row * DDM;
    float* yr = y + (size_t)row * DDM;

    float4 v = reinterpret_cast<const float4*>(xr)[tid];
    red[tid] = v.x + v.y + v.z + v.w; __syncthreads();
    for (int o = 128; o > 0; o >>= 1) { if (tid < o) red[tid] += red[tid + o]; __syncthreads(); }
    const float mean = red[0] * (1.0f / DDM);
    __syncthreads();

    float4 d = make_float4(v.x - mean, v.y - mean, v.z - mean, v.w - mean);
    red[tid] = d.x * d.x + d.y * d.y + d.z * d.z + d.w * d.w; __syncthreads();
    for (int o = 128; o > 0; o >>= 1) { if (tid < o) red[tid] += red[tid + o]; __syncthreads(); }
    const float stdv = sqrtf(red[0] * (1.0f / (DDM - 1)));
    const float a = alpha[0], bta = beta[0];
    const float inv = a / (stdv + 1e-6f);

    float4 o;
    o.x = tf32r(d.x * inv + bta); o.y = tf32r(d.y * inv + bta);
    o.z = tf32r(d.z * inv + bta); o.w = tf32r(d.w * inv + bta);
    reinterpret_cast<float4*>(yr)[tid] = o;
}

// ---------------- softmax over rows of 1024, tf32-rounded probs ----------
__global__ __launch_bounds__(256) void softmax_kernel(float* __restrict__ sc)
{
    __shared__ float red[256];
    float* row = sc + (size_t)blockIdx.x * SSZ;
    const int tid = threadIdx.x;
    float4 v = reinterpret_cast<float4*>(row)[tid];

    float m = fmaxf(fmaxf(v.x, v.y), fmaxf(v.z, v.w));
    red[tid] = m; __syncthreads();
    for (int o = 128; o > 0; o >>= 1) { if (tid < o) red[tid] = fmaxf(red[tid], red[tid + o]); __syncthreads(); }
    const float mx = red[0]; __syncthreads();

    v.x = __expf(v.x - mx); v.y = __expf(v.y - mx);
    v.z = __expf(v.z - mx); v.w = __expf(v.w - mx);
    red[tid] = v.x + v.y + v.z + v.w; __syncthreads();
    for (int o = 128; o > 0; o >>= 1) { if (tid < o) red[tid] += red[tid + o]; __syncthreads(); }
    const float inv = 1.0f / red[0];

    float4 o;
    o.x = tf32r(v.x * inv); o.y = tf32r(v.y * inv);
    o.z = tf32r(v.z * inv); o.w = tf32r(v.w * inv);
    reinterpret_cast<float4*>(row)[tid] = o;
}

// ---------------- transposes ----------------
__global__ void wtrans_kernel(const float* __restrict__ src, float* __restrict__ dst,
                              int R, int C)
{
    __shared__ float t[32][33];
    const int c0 = blockIdx.x * 32, r0 = blockIdx.y * 32;
    const int tx = threadIdx.x, ty = threadIdx.y;
    #pragma unroll
    for (int i = ty; i < 32; i += 8)
        t[i][tx] = src[(size_t)(r0 + i) * C + c0 + tx];
    __syncthreads();
    #pragma unroll
    for (int i = ty; i < 32; i += 8)
        dst[(size_t)(c0 + i) * R + r0 + tx] = tf32r(t[tx][i]);
}

__global__ void vtrans_kernel(const float* __restrict__ qkv, float* __restrict__ vt)
{
    __shared__ float t[32][33];
    const int bh = blockIdx.z, b = bh >> 4, h = bh & 15;
    const int s0 = blockIdx.x * 32, d0 = blockIdx.y * 32;
    const int tx = threadIdx.x, ty = threadIdx.y;
    #pragma unroll
    for (int i = ty; i < 32; i += 8)
        t[i][tx] = qkv[(size_t)(b * SSZ + s0 + i) * QKVLD + 2048 + h * 64 + d0 + tx];
    __syncthreads();
    #pragma unroll
    for (int i = ty; i < 32; i += 8)
        vt[(size_t)bh * 64 * SSZ + (size_t)(d0 + i) * SSZ + s0 + tx] = t[tx][i];
}

__global__ void bcat_kernel(const float* __restrict__ bq, const float* __restrict__ bk,
                            const float* __restrict__ bv, float* __restrict__ dst)
{
    const int i = blockIdx.x * 256 + threadIdx.x;
    if (i < 1024) dst[i] = bq[i];
    else if (i < 2048) dst[i] = bk[i - 1024];
    else dst[i] = bv[i - 2048];
}

// ---------------- launch ----------------
extern "C" void kernel_launch(void* const* d_in, const int* in_sizes, int n_in,
                              void* d_out, int out_size)
{
    const float* x      = (const float*)d_in[0];
    const int*   mask   = (const int*)  d_in[1];
    const float* wq     = (const float*)d_in[2];
    const float* bq     = (const float*)d_in[3];
    const float* wk     = (const float*)d_in[4];
    const float* bk     = (const float*)d_in[5];
    const float* wv     = (const float*)d_in[6];
    const float* bv     = (const float*)d_in[7];
    const float* wo     = (const float*)d_in[8];
    const float* bo     = (const float*)d_in[9];
    const float* w1     = (const float*)d_in[10];
    const float* b1     = (const float*)d_in[11];
    const float* w2     = (const float*)d_in[12];
    const float* b2     = (const float*)d_in[13];
    const float* alpha1 = (const float*)d_in[14];
    const float* beta1  = (const float*)d_in[15];
    const float* alpha2 = (const float*)d_in[16];
    const float* beta2  = (const float*)d_in[17];
    float* out = (float*)d_out;

    const int SMEM128 = 3 * (128 * SA * 4 + 128 * SA * 4);   // 61440
    const int SMEM64  = 3 * (128 * SA * 4 + 64 * SA * 4);    // 46080
    cudaFuncSetAttribute(gemm_mma_kernel,   cudaFuncAttributeMaxDynamicSharedMemorySize, SMEM128);
    cudaFuncSetAttribute(scores_mma_kernel, cudaFuncAttributeMaxDynamicSharedMemorySize, SMEM128);
    cudaFuncSetAttribute(ctx_mma_kernel,    cudaFuncAttributeMaxDynamicSharedMemorySize, SMEM64);

    float *xn, *qkv, *vt, *ctx, *x1, *ff, *sc, *wqkvt, *wot, *w1t, *w2t, *bqkv;
    cudaGetSymbolAddress((void**)&xn,    g_xn);
    cudaGetSymbolAddress((void**)&qkv,   g_qkv);
    cudaGetSymbolAddress((void**)&vt,    g_vt);
    cudaGetSymbolAddress((void**)&ctx,   g_ctx);
    cudaGetSymbolAddress((void**)&x1,    g_x1);
    cudaGetSymbolAddress((void**)&ff,    g_ff);
    cudaGetSymbolAddress((void**)&sc,    g_sc);
    cudaGetSymbolAddress((void**)&wqkvt, g_wqkvt);
    cudaGetSymbolAddress((void**)&wot,   g_wot);
    cudaGetSymbolAddress((void**)&w1t,   g_w1t);
    cudaGetSymbolAddress((void**)&w2t,   g_w2t);
    cudaGetSymbolAddress((void**)&bqkv,  g_bqkv);

    dim3 tb(32, 8);
    // weight transposes (tf32-round once per call)
    wtrans_kernel<<<dim3(32, 32),  tb>>>(wq, wqkvt,               1024, 1024);
    wtrans_kernel<<<dim3(32, 32),  tb>>>(wk, wqkvt + 1024 * 1024, 1024, 1024);
    wtrans_kernel<<<dim3(32, 32),  tb>>>(wv, wqkvt + 2048 * 1024, 1024, 1024);
    wtrans_kernel<<<dim3(32, 32),  tb>>>(wo, wot,                 1024, 1024);
    wtrans_kernel<<<dim3(128, 32), tb>>>(w1, w1t,                 1024, 4096);
    wtrans_kernel<<<dim3(32, 128), tb>>>(w2, w2t,                 4096, 1024);
    bcat_kernel<<<12, 256>>>(bq, bk, bv, bqkv);

    // LN1 + fused QKV projection
    ln_kernel<<<ROWS, 256>>>(x, xn, alpha1, beta1);
    gemm_mma_kernel<<<dim3(24, 32), 256, SMEM128>>>(xn, DDM, wqkvt, bqkv, nullptr,
                                                    qkv, QKVLD, DDM, 0, 1);
    // attention
    vtrans_kernel<<<dim3(32, 2, BHH), tb>>>(qkv, vt);
    scores_mma_kernel<<<dim3(8, 8, BHH), 256, SMEM128>>>(qkv, mask, sc);
    softmax_kernel<<<BHH * SSZ, 256>>>(sc);
    ctx_mma_kernel<<<dim3(1, 8, BHH), 256, SMEM64>>>(sc, vt, ctx);

    // output projection + residual
    gemm_mma_kernel<<<dim3(8, 32), 256, SMEM128>>>(ctx, DDM, wot, bo, x,
                                                   x1, DDM, DDM, 0, 0);
    // LN2 + FFN + residual
    ln_kernel<<<ROWS, 256>>>(x1, xn, alpha2, beta2);
    gemm_mma_kernel<<<dim3(32, 32), 256, SMEM128>>>(xn, DDM, w1t, b1, nullptr,
                                                    ff, DFF, DDM, 1, 1);
    gemm_mma_kernel<<<dim3(8, 32), 256, SMEM128>>>(ff, DFF, w2t, b2, x1,
                                                   out, DDM, DFF, 0, 0);
}

// round 4
// speedup vs baseline: 3.2303x; 1.0491x over previous
#include <cuda_runtime.h>
#include <cuda_fp16.h>
#include <cstdint>

// ---------------- problem dims ----------------
#define BBX   4
#define SSZ   1024
#define DDM   1024
#define HHX   16
#define DFF   4096
#define ROWS  4096          // BBX*SSZ
#define BHH   64            // BBX*HHX
#define QKVLD 3072
#define SA2   40            // padded smem stride (halfs) for BK=32

// ---------------- scratch (static device globals) ----------------
__device__ __half g_xn   [(size_t)ROWS * DDM];
__device__ __half g_qkv  [(size_t)ROWS * QKVLD];
__device__ __half g_vt   [(size_t)BHH * 64 * SSZ];
__device__ __half g_ctx  [(size_t)ROWS * DDM];
__device__ float  g_x1   [(size_t)ROWS * DDM];
__device__ __half g_ff   [(size_t)ROWS * DFF];
__device__ __half g_sc   [(size_t)BHH * SSZ * SSZ];
__device__ __half g_wqkvt[(size_t)QKVLD * DDM];
__device__ __half g_wot  [(size_t)DDM * DDM];
__device__ __half g_w1t  [(size_t)DFF * DDM];
__device__ __half g_w2t  [(size_t)DDM * DFF];
__device__ float  g_bqkv [QKVLD];

// ---------------- helpers ----------------
__device__ __forceinline__ uint32_t smem_u32(const void* p) {
    uint32_t a;
    asm("{ .reg .u64 t; cvta.to.shared.u64 t, %1; cvt.u32.u64 %0, t; }"
        : "=r"(a) : "l"(p));
    return a;
}
__device__ __forceinline__ void cpasync16(uint32_t s, const void* g) {
    asm volatile("cp.async.cg.shared.global [%0], [%1], 16;" :: "r"(s), "l"(g));
}
#define CP_COMMIT() asm volatile("cp.async.commit_group;" ::: "memory")
#define CP_WAIT1()  asm volatile("cp.async.wait_group 1;" ::: "memory")

__device__ __forceinline__ void mma_f16(float (&d)[4],
                                        const uint32_t (&a)[4],
                                        const uint32_t (&b)[2]) {
    asm volatile(
        "mma.sync.aligned.m16n8k16.row.col.f32.f16.f16.f32 "
        "{%0,%1,%2,%3},{%4,%5,%6,%7},{%8,%9},{%0,%1,%2,%3};"
        : "+f"(d[0]), "+f"(d[1]), "+f"(d[2]), "+f"(d[3])
        : "r"(a[0]), "r"(a[1]), "r"(a[2]), "r"(a[3]),
          "r"(b[0]), "r"(b[1]));
}

// ---------------- cp.async tile loader (one BK=32 chunk, halfs) ----------------
template <int NI>
__device__ __forceinline__ void load_chunk(const __half* __restrict__ A, int lda,
                                           const __half* __restrict__ B, int ldb,
                                           int k0, uint32_t sA, uint32_t sB, int tid)
{
    #pragma unroll
    for (int it = 0; it < 2; it++) {          // A: 128 rows * 4 xfers
        const int idx = tid + it * 256;
        const int r = idx >> 2, c = idx & 3;
        cpasync16(sA + (uint32_t)(r * SA2 + c * 8) * 2,
                  A + (size_t)r * lda + k0 + c * 8);
    }
    #pragma unroll
    for (int it = 0; it < (NI * 32 * 4) / 256; it++) {   // B: NI*32 rows
        const int idx = tid + it * 256;
        const int n = idx >> 2, c = idx & 3;
        cpasync16(sB + (uint32_t)(n * SA2 + c * 8) * 2,
                  B + (size_t)n * ldb + k0 + c * 8);
    }
}

// ---------------- mma.sync fp16 mainloop -------------------------------
// block tile 128 x (NI*32); 8 warps (2 m x 4 n), warp tile 64x(NI*8)
template <int NI>
__device__ __forceinline__ void mma_mainloop(const __half* __restrict__ A, int lda,
                                             const __half* __restrict__ B, int ldb,
                                             int K, float (&acc)[4][NI][4], char* dyn)
{
    constexpr int ASZ = 128 * SA2 * 2;        // bytes
    constexpr int BSZ = NI * 32 * SA2 * 2;
    constexpr int STG = ASZ + BSZ;
    const int tid = threadIdx.x;
    const int wid = tid >> 5, lane = tid & 31;
    const int wm = wid >> 2, wn = wid & 3;
    const int gid = lane >> 2, tig = lane & 3;
    const uint32_t sbase = smem_u32(dyn);

    const int nk = K >> 5;
    #pragma unroll
    for (int s = 0; s < 2; s++) {
        if (s < nk)
            load_chunk<NI>(A, lda, B, ldb, s * 32,
                           sbase + s * STG, sbase + s * STG + ASZ, tid);
        CP_COMMIT();
    }

    for (int c = 0; c < nk; c++) {
        CP_WAIT1();
        __syncthreads();
        const int nst = c + 2;
        if (nst < nk) {
            const int s2 = nst % 3;
            load_chunk<NI>(A, lda, B, ldb, nst * 32,
                           sbase + s2 * STG, sbase + s2 * STG + ASZ, tid);
        }
        CP_COMMIT();

        const int s = c % 3;
        const __half* As = (const __half*)(dyn + s * STG);
        const __half* Bs = (const __half*)(dyn + s * STG + ASZ);

        #pragma unroll
        for (int ks = 0; ks < 2; ks++) {      // two k16 steps per BK=32
            const int kofs = ks * 16 + 2 * tig;
            uint32_t afr[4][4];
            #pragma unroll
            for (int mi = 0; mi < 4; mi++) {
                const __half* ar = As + (wm * 64 + mi * 16 + gid) * SA2 + kofs;
                afr[mi][0] = *(const uint32_t*)(ar);
                afr[mi][1] = *(const uint32_t*)(ar + 8 * SA2);
                afr[mi][2] = *(const uint32_t*)(ar + 8);
                afr[mi][3] = *(const uint32_t*)(ar + 8 * SA2 + 8);
            }
            uint32_t bfr[NI][2];
            #pragma unroll
            for (int ni = 0; ni < NI; ni++) {
                const __half* br = Bs + (wn * NI * 8 + ni * 8 + gid) * SA2 + kofs;
                bfr[ni][0] = *(const uint32_t*)(br);
                bfr[ni][1] = *(const uint32_t*)(br + 8);
            }
            #pragma unroll
            for (int mi = 0; mi < 4; mi++)
                #pragma unroll
                for (int ni = 0; ni < NI; ni++)
                    mma_f16(acc[mi][ni], afr[mi], bfr[ni]);
        }
    }
}

// ---------------- dense GEMM: C = A.Bt^T + bias (+relu) (+res) ---------
// OUT_HALF: C is __half* (no residual); else float* (optional residual)
template <int OUT_HALF, int RELU>
__global__ __launch_bounds__(256, 2) void gemm_mma_kernel(
    const __half* __restrict__ A, int lda,
    const __half* __restrict__ Bt,
    const float* __restrict__ bias, const float* __restrict__ res,
    void* __restrict__ Cv, int ldc, int K)
{
    extern __shared__ char dyn[];
    const int mBase = blockIdx.y * 128;
    const int nBase = blockIdx.x * 128;
    const __half* Ab = A + (size_t)mBase * lda;
    const __half* Bb = Bt + (size_t)nBase * K;

    float acc[4][4][4];
    #pragma unroll
    for (int i = 0; i < 4; i++)
        #pragma unroll
        for (int j = 0; j < 4; j++)
            #pragma unroll
            for (int q = 0; q < 4; q++) acc[i][j][q] = 0.f;

    mma_mainloop<4>(Ab, lda, Bb, K, K, acc, dyn);

    const int wid = threadIdx.x >> 5, lane = threadIdx.x & 31;
    const int wm = wid >> 2, wn = wid & 3;
    const int gid = lane >> 2, tig = lane & 3;
    const int mW = mBase + wm * 64;
    const int nW = nBase + wn * 32;

    #pragma unroll
    for (int mi = 0; mi < 4; mi++) {
        #pragma unroll
        for (int half_ = 0; half_ < 2; half_++) {
            const int row = mW + mi * 16 + gid + half_ * 8;
            #pragma unroll
            for (int ni = 0; ni < 4; ni++) {
                const int col = nW + ni * 8 + tig * 2;
                float v0 = acc[mi][ni][half_ * 2 + 0] + bias[col];
                float v1 = acc[mi][ni][half_ * 2 + 1] + bias[col + 1];
                if (RELU) { v0 = fmaxf(v0, 0.f); v1 = fmaxf(v1, 0.f); }
                if (OUT_HALF) {
                    __half* cRow = (__half*)Cv + (size_t)row * ldc;
                    *reinterpret_cast<__half2*>(cRow + col) = __floats2half2_rn(v0, v1);
                } else {
                    float* cRow = (float*)Cv + (size_t)row * ldc;
                    if (res) {
                        const float* rRow = res + (size_t)row * ldc;
                        v0 += rRow[col]; v1 += rRow[col + 1];
                    }
                    *reinterpret_cast<float2*>(cRow + col) = make_float2(v0, v1);
                }
            }
        }
    }
}

// ---------------- scores: S[bh,m,n] = (q_m.k_n)/8, masked, half out ----
__global__ __launch_bounds__(256, 2) void scores_mma_kernel(
    const __half* __restrict__ qkv, const int* __restrict__ mask,
    __half* __restrict__ sc)
{
    extern __shared__ char dyn[];
    const int bh = blockIdx.z, b = bh >> 4, h = bh & 15;
    const int mBase = blockIdx.y * 128;
    const int nBase = blockIdx.x * 128;
    const __half* Ab = qkv + ((size_t)(b * SSZ + mBase)) * QKVLD + h * 64;          // q
    const __half* Bb = qkv + ((size_t)(b * SSZ + nBase)) * QKVLD + 1024 + h * 64;   // k

    float acc[4][4][4];
    #pragma unroll
    for (int i = 0; i < 4; i++)
        #pragma unroll
        for (int j = 0; j < 4; j++)
            #pragma unroll
            for (int q = 0; q < 4; q++) acc[i][j][q] = 0.f;

    mma_mainloop<4>(Ab, QKVLD, Bb, QKVLD, 64, acc, dyn);

    const int wid = threadIdx.x >> 5, lane = threadIdx.x & 31;
    const int wm = wid >> 2, wn = wid & 3;
    const int gid = lane >> 2, tig = lane & 3;
    const int mW = mBase + wm * 64;
    const int nW = nBase + wn * 32;
    const int* mrow = mask + b * SSZ;

    #pragma unroll
    for (int mi = 0; mi < 4; mi++) {
        #pragma unroll
        for (int half_ = 0; half_ < 2; half_++) {
            const int row = mW + mi * 16 + gid + half_ * 8;
            __half* cRow = sc + ((size_t)bh * SSZ + row) * SSZ;
            #pragma unroll
            for (int ni = 0; ni < 4; ni++) {
                const int col = nW + ni * 8 + tig * 2;
                float v0 = acc[mi][ni][half_ * 2 + 0] * 0.125f;
                float v1 = acc[mi][ni][half_ * 2 + 1] * 0.125f;
                if (mrow[col] == 0)     v0 = -60000.f;
                if (mrow[col + 1] == 0) v1 = -60000.f;
                *reinterpret_cast<__half2*>(cRow + col) = __floats2half2_rn(v0, v1);
            }
        }
    }
}

// ---------------- ctx: ctx[b*S+m, h*64+n] = attn[bh,m,:].vt[bh,n,:] ----
__global__ __launch_bounds__(256, 2) void ctx_mma_kernel(
    const __half* __restrict__ attn, const __half* __restrict__ vt,
    __half* __restrict__ ctx)
{
    extern __shared__ char dyn[];
    const int bh = blockIdx.z, b = bh >> 4, h = bh & 15;
    const int mBase = blockIdx.y * 128;
    const __half* Ab = attn + ((size_t)bh * SSZ + mBase) * SSZ;
    const __half* Bb = vt + (size_t)bh * 64 * SSZ;

    float acc[4][2][4];
    #pragma unroll
    for (int i = 0; i < 4; i++)
        #pragma unroll
        for (int j = 0; j < 2; j++)
            #pragma unroll
            for (int q = 0; q < 4; q++) acc[i][j][q] = 0.f;

    mma_mainloop<2>(Ab, SSZ, Bb, SSZ, SSZ, acc, dyn);

    const int wid = threadIdx.x >> 5, lane = threadIdx.x & 31;
    const int wm = wid >> 2, wn = wid & 3;
    const int gid = lane >> 2, tig = lane & 3;
    const int mW = mBase + wm * 64;
    const int nW = wn * 16;

    #pragma unroll
    for (int mi = 0; mi < 4; mi++) {
        #pragma unroll
        for (int half_ = 0; half_ < 2; half_++) {
            const int row = mW + mi * 16 + gid + half_ * 8;
            __half* oRow = ctx + (size_t)(b * SSZ + row) * DDM + h * 64;
            #pragma unroll
            for (int ni = 0; ni < 2; ni++) {
                const int col = nW + ni * 8 + tig * 2;
                *reinterpret_cast<__half2*>(oRow + col) =
                    __floats2half2_rn(acc[mi][ni][half_ * 2 + 0],
                                      acc[mi][ni][half_ * 2 + 1]);
            }
        }
    }
}

// ---------------- LayerNorm (ddof=1, eps on std, scalar a/b), half out --
__global__ __launch_bounds__(256) void ln_kernel(const float* __restrict__ x,
                                                 __half* __restrict__ y,
                                                 const float* __restrict__ alpha,
                                                 const float* __restrict__ beta)
{
    __shared__ float red[256];
    const int row = blockIdx.x, tid = threadIdx.x;
    const float* xr = x + (size_t)row * DDM;
    __half* yr = y + (size_t)row * DDM;

    float4 v = reinterpret_cast<const float4*>(xr)[tid];
    red[tid] = v.x + v.y + v.z + v.w; __syncthreads();
    for (int o = 128; o > 0; o >>= 1) { if (tid < o) red[tid] += red[tid + o]; __syncthreads(); }
    const float mean = red[0] * (1.0f / DDM);
    __syncthreads();

    float4 d = make_float4(v.x - mean, v.y - mean, v.z - mean, v.w - mean);
    red[tid] = d.x * d.x + d.y * d.y + d.z * d.z + d.w * d.w; __syncthreads();
    for (int o = 128; o > 0; o >>= 1) { if (tid < o) red[tid] += red[tid + o]; __syncthreads(); }
    const float stdv = sqrtf(red[0] * (1.0f / (DDM - 1)));
    const float a = alpha[0], bta = beta[0];
    const float inv = a / (stdv + 1e-6f);

    __half2 o0 = __floats2half2_rn(d.x * inv + bta, d.y * inv + bta);
    __half2 o1 = __floats2half2_rn(d.z * inv + bta, d.w * inv + bta);
    uint2 pk;
    pk.x = *reinterpret_cast<uint32_t*>(&o0);
    pk.y = *reinterpret_cast<uint32_t*>(&o1);
    reinterpret_cast<uint2*>(yr)[tid] = pk;
}

// ---------------- softmax over rows of 1024 halfs ------------------------
__global__ __launch_bounds__(256) void softmax_kernel(__half* __restrict__ sc)
{
    __shared__ float red[256];
    __half* row = sc + (size_t)blockIdx.x * SSZ;
    const int tid = threadIdx.x;

    uint2 raw = reinterpret_cast<uint2*>(row)[tid];
    __half2 h0 = *reinterpret_cast<__half2*>(&raw.x);
    __half2 h1 = *reinterpret_cast<__half2*>(&raw.y);
    float4 v = make_float4(__low2float(h0), __high2float(h0),
                           __low2float(h1), __high2float(h1));

    float m = fmaxf(fmaxf(v.x, v.y), fmaxf(v.z, v.w));
    red[tid] = m; __syncthreads();
    for (int o = 128; o > 0; o >>= 1) { if (tid < o) red[tid] = fmaxf(red[tid], red[tid + o]); __syncthreads(); }
    const float mx = red[0]; __syncthreads();

    v.x = __expf(v.x - mx); v.y = __expf(v.y - mx);
    v.z = __expf(v.z - mx); v.w = __expf(v.w - mx);
    red[tid] = v.x + v.y + v.z + v.w; __syncthreads();
    for (int o = 128; o > 0; o >>= 1) { if (tid < o) red[tid] += red[tid + o]; __syncthreads(); }
    const float inv = 1.0f / red[0];

    __half2 o0 = __floats2half2_rn(v.x * inv, v.y * inv);
    __half2 o1 = __floats2half2_rn(v.z * inv, v.w * inv);
    uint2 pk;
    pk.x = *reinterpret_cast<uint32_t*>(&o0);
    pk.y = *reinterpret_cast<uint32_t*>(&o1);
    reinterpret_cast<uint2*>(row)[tid] = pk;
}

// ---------------- transposes ----------------
__global__ void wtrans_kernel(const float* __restrict__ src, __half* __restrict__ dst,
                              int R, int C)
{
    __shared__ float t[32][33];
    const int c0 = blockIdx.x * 32, r0 = blockIdx.y * 32;
    const int tx = threadIdx.x, ty = threadIdx.y;
    #pragma unroll
    for (int i = ty; i < 32; i += 8)
        t[i][tx] = src[(size_t)(r0 + i) * C + c0 + tx];
    __syncthreads();
    #pragma unroll
    for (int i = ty; i < 32; i += 8)
        dst[(size_t)(c0 + i) * R + r0 + tx] = __float2half_rn(t[tx][i]);
}

__global__ void vtrans_kernel(const __half* __restrict__ qkv, __half* __restrict__ vt)
{
    __shared__ __half t[32][34];
    const int bh = blockIdx.z, b = bh >> 4, h = bh & 15;
    const int s0 = blockIdx.x * 32, d0 = blockIdx.y * 32;
    const int tx = threadIdx.x, ty = threadIdx.y;
    #pragma unroll
    for (int i = ty; i < 32; i += 8)
        t[i][tx] = qkv[(size_t)(b * SSZ + s0 + i) * QKVLD + 2048 + h * 64 + d0 + tx];
    __syncthreads();
    #pragma unroll
    for (int i = ty; i < 32; i += 8)
        vt[(size_t)bh * 64 * SSZ + (size_t)(d0 + i) * SSZ + s0 + tx] = t[tx][i];
}

__global__ void bcat_kernel(const float* __restrict__ bq, const float* __restrict__ bk,
                            const float* __restrict__ bv, float* __restrict__ dst)
{
    const int i = blockIdx.x * 256 + threadIdx.x;
    if (i < 1024) dst[i] = bq[i];
    else if (i < 2048) dst[i] = bk[i - 1024];
    else dst[i] = bv[i - 2048];
}

// ---------------- launch ----------------
extern "C" void kernel_launch(void* const* d_in, const int* in_sizes, int n_in,
                              void* d_out, int out_size)
{
    const float* x      = (const float*)d_in[0];
    const int*   mask   = (const int*)  d_in[1];
    const float* wq     = (const float*)d_in[2];
    const float* bq     = (const float*)d_in[3];
    const float* wk     = (const float*)d_in[4];
    const float* bk     = (const float*)d_in[5];
    const float* wv     = (const float*)d_in[6];
    const float* bv     = (const float*)d_in[7];
    const float* wo     = (const float*)d_in[8];
    const float* bo     = (const float*)d_in[9];
    const float* w1     = (const float*)d_in[10];
    const float* b1     = (const float*)d_in[11];
    const float* w2     = (const float*)d_in[12];
    const float* b2     = (const float*)d_in[13];
    const float* alpha1 = (const float*)d_in[14];
    const float* beta1  = (const float*)d_in[15];
    const float* alpha2 = (const float*)d_in[16];
    const float* beta2  = (const float*)d_in[17];
    float* out = (float*)d_out;

    // smem: 3 stages * (A 128*40*2 + B {128|64}*40*2)
    const int SMEM128 = 3 * (128 * SA2 * 2 + 128 * SA2 * 2);   // 61440
    const int SMEM64  = 3 * (128 * SA2 * 2 + 64 * SA2 * 2);    // 46080
    cudaFuncSetAttribute((const void*)gemm_mma_kernel<1, 0>, cudaFuncAttributeMaxDynamicSharedMemorySize, SMEM128);
    cudaFuncSetAttribute((const void*)gemm_mma_kernel<1, 1>, cudaFuncAttributeMaxDynamicSharedMemorySize, SMEM128);
    cudaFuncSetAttribute((const void*)gemm_mma_kernel<0, 0>, cudaFuncAttributeMaxDynamicSharedMemorySize, SMEM128);
    cudaFuncSetAttribute((const void*)scores_mma_kernel,     cudaFuncAttributeMaxDynamicSharedMemorySize, SMEM128);
    cudaFuncSetAttribute((const void*)ctx_mma_kernel,        cudaFuncAttributeMaxDynamicSharedMemorySize, SMEM64);

    __half *xn, *qkv, *vt, *ctx, *ff, *sc, *wqkvt, *wot, *w1t, *w2t;
    float *x1, *bqkv;
    cudaGetSymbolAddress((void**)&xn,    g_xn);
    cudaGetSymbolAddress((void**)&qkv,   g_qkv);
    cudaGetSymbolAddress((void**)&vt,    g_vt);
    cudaGetSymbolAddress((void**)&ctx,   g_ctx);
    cudaGetSymbolAddress((void**)&x1,    g_x1);
    cudaGetSymbolAddress((void**)&ff,    g_ff);
    cudaGetSymbolAddress((void**)&sc,    g_sc);
    cudaGetSymbolAddress((void**)&wqkvt, g_wqkvt);
    cudaGetSymbolAddress((void**)&wot,   g_wot);
    cudaGetSymbolAddress((void**)&w1t,   g_w1t);
    cudaGetSymbolAddress((void**)&w2t,   g_w2t);
    cudaGetSymbolAddress((void**)&bqkv,  g_bqkv);

    dim3 tb(32, 8);
    // weight transposes fp32 -> fp16 K-major
    wtrans_kernel<<<dim3(32, 32),  tb>>>(wq, wqkvt,               1024, 1024);
    wtrans_kernel<<<dim3(32, 32),  tb>>>(wk, wqkvt + 1024 * 1024, 1024, 1024);
    wtrans_kernel<<<dim3(32, 32),  tb>>>(wv, wqkvt + 2048 * 1024, 1024, 1024);
    wtrans_kernel<<<dim3(32, 32),  tb>>>(wo, wot,                 1024, 1024);
    wtrans_kernel<<<dim3(128, 32), tb>>>(w1, w1t,                 1024, 4096);
    wtrans_kernel<<<dim3(32, 128), tb>>>(w2, w2t,                 4096, 1024);
    bcat_kernel<<<12, 256>>>(bq, bk, bv, bqkv);

    // LN1 + fused QKV projection (half out)
    ln_kernel<<<ROWS, 256>>>(x, xn, alpha1, beta1);
    gemm_mma_kernel<1, 0><<<dim3(24, 32), 256, SMEM128>>>(xn, DDM, wqkvt, bqkv,
                                                          nullptr, qkv, QKVLD, DDM);
    // attention
    vtrans_kernel<<<dim3(32, 2, BHH), tb>>>(qkv, vt);
    scores_mma_kernel<<<dim3(8, 8, BHH), 256, SMEM128>>>(qkv, mask, sc);
    softmax_kernel<<<BHH * SSZ, 256>>>(sc);
    ctx_mma_kernel<<<dim3(1, 8, BHH), 256, SMEM64>>>(sc, vt, ctx);

    // output projection + residual (float out)
    gemm_mma_kernel<0, 0><<<dim3(8, 32), 256, SMEM128>>>(ctx, DDM, wot, bo,
                                                         x, x1, DDM, DDM);
    // LN2 + FFN + residual
    ln_kernel<<<ROWS, 256>>>(x1, xn, alpha2, beta2);
    gemm_mma_kernel<1, 1><<<dim3(32, 32), 256, SMEM128>>>(xn, DDM, w1t, b1,
                                                          nullptr, ff, DFF, DDM);
    gemm_mma_kernel<0, 0><<<dim3(8, 32), 256, SMEM128>>>(ff, DFF, w2t, b2,
                                                         x1, out, DDM, DFF);
}

// round 5
// speedup vs baseline: 5.5812x; 1.7278x over previous
#include <cuda_runtime.h>
#include <cuda_fp16.h>
#include <cstdint>

// ---------------- problem dims ----------------
#define BBX   4
#define SSZ   1024
#define DDM   1024
#define HHX   16
#define DFF   4096
#define ROWS  4096          // BBX*SSZ
#define BHH   64            // BBX*HHX
#define QKVLD 3072
#define SA2   40            // padded smem stride (halfs) for BK=32

// ---------------- scratch (static device globals) ----------------
__device__ __half g_xn   [(size_t)ROWS * DDM];
__device__ __half g_qkv  [(size_t)ROWS * QKVLD];
__device__ __half g_vt   [(size_t)BHH * 64 * SSZ];
__device__ __half g_ctx  [(size_t)ROWS * DDM];
__device__ float  g_x1   [(size_t)ROWS * DDM];
__device__ __half g_ff   [(size_t)ROWS * DFF];
__device__ __half g_sc   [(size_t)BHH * SSZ * SSZ];
__device__ __half g_wqkvt[(size_t)QKVLD * DDM];
__device__ __half g_wot  [(size_t)DDM * DDM];
__device__ __half g_w1t  [(size_t)DFF * DDM];
__device__ __half g_w2t  [(size_t)DDM * DFF];
__device__ float  g_bqkv [QKVLD];

// ---------------- helpers ----------------
__device__ __forceinline__ uint32_t smem_u32(const void* p) {
    uint32_t a;
    asm("{ .reg .u64 t; cvta.to.shared.u64 t, %1; cvt.u32.u64 %0, t; }"
        : "=r"(a) : "l"(p));
    return a;
}
__device__ __forceinline__ void cpasync16(uint32_t s, const void* g) {
    asm volatile("cp.async.cg.shared.global [%0], [%1], 16;" :: "r"(s), "l"(g));
}
#define CP_COMMIT() asm volatile("cp.async.commit_group;" ::: "memory")
#define CP_WAIT1()  asm volatile("cp.async.wait_group 1;" ::: "memory")

__device__ __forceinline__ void ldsm4(uint32_t addr, uint32_t& r0, uint32_t& r1,
                                      uint32_t& r2, uint32_t& r3) {
    asm volatile("ldmatrix.sync.aligned.m8n8.x4.shared.b16 {%0,%1,%2,%3}, [%4];"
                 : "=r"(r0), "=r"(r1), "=r"(r2), "=r"(r3) : "r"(addr));
}

__device__ __forceinline__ void mma_f16(float (&d)[4],
                                        const uint32_t (&a)[4],
                                        const uint32_t (&b)[2]) {
    asm volatile(
        "mma.sync.aligned.m16n8k16.row.col.f32.f16.f16.f32 "
        "{%0,%1,%2,%3},{%4,%5,%6,%7},{%8,%9},{%0,%1,%2,%3};"
        : "+f"(d[0]), "+f"(d[1]), "+f"(d[2]), "+f"(d[3])
        : "r"(a[0]), "r"(a[1]), "r"(a[2]), "r"(a[3]),
          "r"(b[0]), "r"(b[1]));
}

// ---------------- cp.async tile loader (one BK=32 chunk, halfs) ----------------
template <int NI>
__device__ __forceinline__ void load_chunk(const __half* __restrict__ A, int lda,
                                           const __half* __restrict__ B, int ldb,
                                           int k0, uint32_t sA, uint32_t sB, int tid)
{
    #pragma unroll
    for (int it = 0; it < 2; it++) {          // A: 128 rows * 4 xfers
        const int idx = tid + it * 256;
        const int r = idx >> 2, c = idx & 3;
        cpasync16(sA + (uint32_t)(r * SA2 + c * 8) * 2,
                  A + (size_t)r * lda + k0 + c * 8);
    }
    #pragma unroll
    for (int it = 0; it < (NI * 32 * 4) / 256; it++) {   // B: NI*32 rows
        const int idx = tid + it * 256;
        const int n = idx >> 2, c = idx & 3;
        cpasync16(sB + (uint32_t)(n * SA2 + c * 8) * 2,
                  B + (size_t)n * ldb + k0 + c * 8);
    }
}

// ---------------- mma.sync fp16 mainloop (ldmatrix fragments) ----------
// block tile 128 x (NI*32); 8 warps (2 m x 4 n), warp tile 64x(NI*8)
template <int NI>
__device__ __forceinline__ void mma_mainloop(const __half* __restrict__ A, int lda,
                                             const __half* __restrict__ B, int ldb,
                                             int K, float (&acc)[4][NI][4], char* dyn)
{
    constexpr int ASZ = 128 * SA2 * 2;        // bytes
    constexpr int BSZ = NI * 32 * SA2 * 2;
    constexpr int STG = ASZ + BSZ;
    const int tid = threadIdx.x;
    const int wid = tid >> 5, lane = tid & 31;
    const int wm = wid >> 2, wn = wid & 3;
    const uint32_t sbase = smem_u32(dyn);

    // ldmatrix lane offsets (halfs)
    // A x4: matrices (rows0-7,k0-7),(rows8-15,k0-7),(rows0-7,k8-15),(rows8-15,k8-15)
    const int a_row = wm * 64 + (lane & 15);
    const int a_col = (lane >> 4) << 3;
    const uint32_t aOff = (uint32_t)(a_row * SA2 + a_col) * 2;
    // B x4 covers two ni (8 rows each): m0=(n0-7,k0-7) m1=(n0-7,k8-15) m2=(n8-15,k0-7) m3=(n8-15,k8-15)
    const int b_row = wn * (NI * 8) + (lane & 7) + ((lane >> 4) << 3);
    const int b_col = ((lane >> 3) & 1) << 3;
    const uint32_t bOff = (uint32_t)(b_row * SA2 + b_col) * 2;

    const int nk = K >> 5;
    #pragma unroll
    for (int s = 0; s < 2; s++) {
        if (s < nk)
            load_chunk<NI>(A, lda, B, ldb, s * 32,
                           sbase + s * STG, sbase + s * STG + ASZ, tid);
        CP_COMMIT();
    }

    for (int c = 0; c < nk; c++) {
        CP_WAIT1();
        __syncthreads();
        const int nst = c + 2;
        if (nst < nk) {
            const int s2 = nst % 3;
            load_chunk<NI>(A, lda, B, ldb, nst * 32,
                           sbase + s2 * STG, sbase + s2 * STG + ASZ, tid);
        }
        CP_COMMIT();

        const int s = c % 3;
        const uint32_t aBase = sbase + s * STG + aOff;
        const uint32_t bBase = sbase + s * STG + ASZ + bOff;

        #pragma unroll
        for (int ks = 0; ks < 2; ks++) {      // two k16 steps per BK=32
            const uint32_t kb = (uint32_t)(ks * 16) * 2;
            uint32_t afr[4][4];
            #pragma unroll
            for (int mi = 0; mi < 4; mi++)
                ldsm4(aBase + kb + (uint32_t)(mi * 16 * SA2) * 2,
                      afr[mi][0], afr[mi][1], afr[mi][2], afr[mi][3]);
            uint32_t bfr[NI][2];
            #pragma unroll
            for (int np = 0; np < NI / 2; np++)
                ldsm4(bBase + kb + (uint32_t)(np * 16 * SA2) * 2,
                      bfr[2 * np][0], bfr[2 * np][1],
                      bfr[2 * np + 1][0], bfr[2 * np + 1][1]);
            #pragma unroll
            for (int mi = 0; mi < 4; mi++)
                #pragma unroll
                for (int ni = 0; ni < NI; ni++)
                    mma_f16(acc[mi][ni], afr[mi], bfr[ni]);
        }
    }
}

// ---------------- dense GEMM: C = A.Bt^T + bias (+relu) (+res) ---------
template <int OUT_HALF, int RELU>
__global__ __launch_bounds__(256, 2) void gemm_mma_kernel(
    const __half* __restrict__ A, int lda,
    const __half* __restrict__ Bt,
    const float* __restrict__ bias, const float* __restrict__ res,
    void* __restrict__ Cv, int ldc, int K)
{
    extern __shared__ char dyn[];
    const int mBase = blockIdx.y * 128;
    const int nBase = blockIdx.x * 128;
    const __half* Ab = A + (size_t)mBase * lda;
    const __half* Bb = Bt + (size_t)nBase * K;

    float acc[4][4][4];
    #pragma unroll
    for (int i = 0; i < 4; i++)
        #pragma unroll
        for (int j = 0; j < 4; j++)
            #pragma unroll
            for (int q = 0; q < 4; q++) acc[i][j][q] = 0.f;

    mma_mainloop<4>(Ab, lda, Bb, K, K, acc, dyn);

    const int wid = threadIdx.x >> 5, lane = threadIdx.x & 31;
    const int wm = wid >> 2, wn = wid & 3;
    const int gid = lane >> 2, tig = lane & 3;
    const int mW = mBase + wm * 64;
    const int nW = nBase + wn * 32;

    #pragma unroll
    for (int mi = 0; mi < 4; mi++) {
        #pragma unroll
        for (int half_ = 0; half_ < 2; half_++) {
            const int row = mW + mi * 16 + gid + half_ * 8;
            #pragma unroll
            for (int ni = 0; ni < 4; ni++) {
                const int col = nW + ni * 8 + tig * 2;
                float v0 = acc[mi][ni][half_ * 2 + 0] + bias[col];
                float v1 = acc[mi][ni][half_ * 2 + 1] + bias[col + 1];
                if (RELU) { v0 = fmaxf(v0, 0.f); v1 = fmaxf(v1, 0.f); }
                if (OUT_HALF) {
                    __half* cRow = (__half*)Cv + (size_t)row * ldc;
                    *reinterpret_cast<__half2*>(cRow + col) = __floats2half2_rn(v0, v1);
                } else {
                    float* cRow = (float*)Cv + (size_t)row * ldc;
                    if (res) {
                        const float* rRow = res + (size_t)row * ldc;
                        v0 += rRow[col]; v1 += rRow[col + 1];
                    }
                    *reinterpret_cast<float2*>(cRow + col) = make_float2(v0, v1);
                }
            }
        }
    }
}

// ---------------- scores: S[bh,m,n] = (q_m.k_n)/8, masked, half out ----
__global__ __launch_bounds__(256, 2) void scores_mma_kernel(
    const __half* __restrict__ qkv, const int* __restrict__ mask,
    __half* __restrict__ sc)
{
    extern __shared__ char dyn[];
    const int bh = blockIdx.z, b = bh >> 4, h = bh & 15;
    const int mBase = blockIdx.y * 128;
    const int nBase = blockIdx.x * 128;
    const __half* Ab = qkv + ((size_t)(b * SSZ + mBase)) * QKVLD + h * 64;          // q
    const __half* Bb = qkv + ((size_t)(b * SSZ + nBase)) * QKVLD + 1024 + h * 64;   // k

    float acc[4][4][4];
    #pragma unroll
    for (int i = 0; i < 4; i++)
        #pragma unroll
        for (int j = 0; j < 4; j++)
            #pragma unroll
            for (int q = 0; q < 4; q++) acc[i][j][q] = 0.f;

    mma_mainloop<4>(Ab, QKVLD, Bb, QKVLD, 64, acc, dyn);

    const int wid = threadIdx.x >> 5, lane = threadIdx.x & 31;
    const int wm = wid >> 2, wn = wid & 3;
    const int gid = lane >> 2, tig = lane & 3;
    const int mW = mBase + wm * 64;
    const int nW = nBase + wn * 32;
    const int* mrow = mask + b * SSZ;

    #pragma unroll
    for (int mi = 0; mi < 4; mi++) {
        #pragma unroll
        for (int half_ = 0; half_ < 2; half_++) {
            const int row = mW + mi * 16 + gid + half_ * 8;
            __half* cRow = sc + ((size_t)bh * SSZ + row) * SSZ;
            #pragma unroll
            for (int ni = 0; ni < 4; ni++) {
                const int col = nW + ni * 8 + tig * 2;
                float v0 = acc[mi][ni][half_ * 2 + 0] * 0.125f;
                float v1 = acc[mi][ni][half_ * 2 + 1] * 0.125f;
                if (mrow[col] == 0)     v0 = -60000.f;
                if (mrow[col + 1] == 0) v1 = -60000.f;
                *reinterpret_cast<__half2*>(cRow + col) = __floats2half2_rn(v0, v1);
            }
        }
    }
}

// ---------------- ctx: ctx[b*S+m, h*64+n] = attn[bh,m,:].vt[bh,n,:] ----
__global__ __launch_bounds__(256, 2) void ctx_mma_kernel(
    const __half* __restrict__ attn, const __half* __restrict__ vt,
    __half* __restrict__ ctx)
{
    extern __shared__ char dyn[];
    const int bh = blockIdx.z, b = bh >> 4, h = bh & 15;
    const int mBase = blockIdx.y * 128;
    const __half* Ab = attn + ((size_t)bh * SSZ + mBase) * SSZ;
    const __half* Bb = vt + (size_t)bh * 64 * SSZ;

    float acc[4][2][4];
    #pragma unroll
    for (int i = 0; i < 4; i++)
        #pragma unroll
        for (int j = 0; j < 2; j++)
            #pragma unroll
            for (int q = 0; q < 4; q++) acc[i][j][q] = 0.f;

    mma_mainloop<2>(Ab, SSZ, Bb, SSZ, SSZ, acc, dyn);

    const int wid = threadIdx.x >> 5, lane = threadIdx.x & 31;
    const int wm = wid >> 2, wn = wid & 3;
    const int gid = lane >> 2, tig = lane & 3;
    const int mW = mBase + wm * 64;
    const int nW = wn * 16;

    #pragma unroll
    for (int mi = 0; mi < 4; mi++) {
        #pragma unroll
        for (int half_ = 0; half_ < 2; half_++) {
            const int row = mW + mi * 16 + gid + half_ * 8;
            __half* oRow = ctx + (size_t)(b * SSZ + row) * DDM + h * 64;
            #pragma unroll
            for (int ni = 0; ni < 2; ni++) {
                const int col = nW + ni * 8 + tig * 2;
                *reinterpret_cast<__half2*>(oRow + col) =
                    __floats2half2_rn(acc[mi][ni][half_ * 2 + 0],
                                      acc[mi][ni][half_ * 2 + 1]);
            }
        }
    }
}

// ---------------- LayerNorm (ddof=1, eps on std, scalar a/b), half out --
__global__ __launch_bounds__(256) void ln_kernel(const float* __restrict__ x,
                                                 __half* __restrict__ y,
                                                 const float* __restrict__ alpha,
                                                 const float* __restrict__ beta)
{
    __shared__ float red[256];
    const int row = blockIdx.x, tid = threadIdx.x;
    const float* xr = x + (size_t)row * DDM;
    __half* yr = y + (size_t)row * DDM;

    float4 v = reinterpret_cast<const float4*>(xr)[tid];
    red[tid] = v.x + v.y + v.z + v.w; __syncthreads();
    for (int o = 128; o > 0; o >>= 1) { if (tid < o) red[tid] += red[tid + o]; __syncthreads(); }
    const float mean = red[0] * (1.0f / DDM);
    __syncthreads();

    float4 d = make_float4(v.x - mean, v.y - mean, v.z - mean, v.w - mean);
    red[tid] = d.x * d.x + d.y * d.y + d.z * d.z + d.w * d.w; __syncthreads();
    for (int o = 128; o > 0; o >>= 1) { if (tid < o) red[tid] += red[tid + o]; __syncthreads(); }
    const float stdv = sqrtf(red[0] * (1.0f / (DDM - 1)));
    const float a = alpha[0], bta = beta[0];
    const float inv = a / (stdv + 1e-6f);

    __half2 o0 = __floats2half2_rn(d.x * inv + bta, d.y * inv + bta);
    __half2 o1 = __floats2half2_rn(d.z * inv + bta, d.w * inv + bta);
    uint2 pk;
    pk.x = *reinterpret_cast<uint32_t*>(&o0);
    pk.y = *reinterpret_cast<uint32_t*>(&o1);
    reinterpret_cast<uint2*>(yr)[tid] = pk;
}

// ---------------- softmax over rows of 1024 halfs ------------------------
__global__ __launch_bounds__(256) void softmax_kernel(__half* __restrict__ sc)
{
    __shared__ float red[256];
    __half* row = sc + (size_t)blockIdx.x * SSZ;
    const int tid = threadIdx.x;

    uint2 raw = reinterpret_cast<uint2*>(row)[tid];
    __half2 h0 = *reinterpret_cast<__half2*>(&raw.x);
    __half2 h1 = *reinterpret_cast<__half2*>(&raw.y);
    float4 v = make_float4(__low2float(h0), __high2float(h0),
                           __low2float(h1), __high2float(h1));

    float m = fmaxf(fmaxf(v.x, v.y), fmaxf(v.z, v.w));
    red[tid] = m; __syncthreads();
    for (int o = 128; o > 0; o >>= 1) { if (tid < o) red[tid] = fmaxf(red[tid], red[tid + o]); __syncthreads(); }
    const float mx = red[0]; __syncthreads();

    v.x = __expf(v.x - mx); v.y = __expf(v.y - mx);
    v.z = __expf(v.z - mx); v.w = __expf(v.w - mx);
    red[tid] = v.x + v.y + v.z + v.w; __syncthreads();
    for (int o = 128; o > 0; o >>= 1) { if (tid < o) red[tid] += red[tid + o]; __syncthreads(); }
    const float inv = 1.0f / red[0];

    __half2 o0 = __floats2half2_rn(v.x * inv, v.y * inv);
    __half2 o1 = __floats2half2_rn(v.z * inv, v.w * inv);
    uint2 pk;
    pk.x = *reinterpret_cast<uint32_t*>(&o0);
    pk.y = *reinterpret_cast<uint32_t*>(&o1);
    reinterpret_cast<uint2*>(row)[tid] = pk;
}

// ---------------- merged weight transpose (all 6 matrices, 1 launch) -----
// tiles: [0,3072): wq/wk/wv -> wqkvt ; [3072,4096): wo ; [4096,8192): w1 ; [8192,12288): w2
__global__ void wtrans_all_kernel(const float* __restrict__ wq, const float* __restrict__ wk,
                                  const float* __restrict__ wv, const float* __restrict__ wo,
                                  const float* __restrict__ w1, const float* __restrict__ w2,
                                  __half* __restrict__ wqkvt, __half* __restrict__ wot,
                                  __half* __restrict__ w1t,   __half* __restrict__ w2t)
{
    __shared__ float t[32][33];
    int tIdx = blockIdx.x;
    const float* src; __half* dst; int R, C;
    if (tIdx < 3072) {
        const int m = tIdx >> 10;
        src = (m == 0) ? wq : (m == 1) ? wk : wv;
        dst = wqkvt + (size_t)m * 1024 * 1024;
        R = 1024; C = 1024; tIdx &= 1023;
    } else if (tIdx < 4096) {
        src = wo; dst = wot; R = 1024; C = 1024; tIdx -= 3072;
    } else if (tIdx < 8192) {
        src = w1; dst = w1t; R = 1024; C = 4096; tIdx -= 4096;
    } else {
        src = w2; dst = w2t; R = 4096; C = 1024; tIdx -= 8192;
    }
    const int nCx = C >> 5;
    const int c0 = (tIdx % nCx) * 32, r0 = (tIdx / nCx) * 32;
    const int tx = threadIdx.x, ty = threadIdx.y;
    #pragma unroll
    for (int i = ty; i < 32; i += 8)
        t[i][tx] = src[(size_t)(r0 + i) * C + c0 + tx];
    __syncthreads();
    #pragma unroll
    for (int i = ty; i < 32; i += 8)
        dst[(size_t)(c0 + i) * R + r0 + tx] = __float2half_rn(t[tx][i]);
}

__global__ void vtrans_kernel(const __half* __restrict__ qkv, __half* __restrict__ vt)
{
    __shared__ __half t[32][34];
    const int bh = blockIdx.z, b = bh >> 4, h = bh & 15;
    const int s0 = blockIdx.x * 32, d0 = blockIdx.y * 32;
    const int tx = threadIdx.x, ty = threadIdx.y;
    #pragma unroll
    for (int i = ty; i < 32; i += 8)
        t[i][tx] = qkv[(size_t)(b * SSZ + s0 + i) * QKVLD + 2048 + h * 64 + d0 + tx];
    __syncthreads();
    #pragma unroll
    for (int i = ty; i < 32; i += 8)
        vt[(size_t)bh * 64 * SSZ + (size_t)(d0 + i) * SSZ + s0 + tx] = t[tx][i];
}

__global__ void bcat_kernel(const float* __restrict__ bq, const float* __restrict__ bk,
                            const float* __restrict__ bv, float* __restrict__ dst)
{
    const int i = blockIdx.x * 256 + threadIdx.x;
    if (i < 1024) dst[i] = bq[i];
    else if (i < 2048) dst[i] = bk[i - 1024];
    else dst[i] = bv[i - 2048];
}

// ---------------- launch ----------------
extern "C" void kernel_launch(void* const* d_in, const int* in_sizes, int n_in,
                              void* d_out, int out_size)
{
    const float* x      = (const float*)d_in[0];
    const int*   mask   = (const int*)  d_in[1];
    const float* wq     = (const float*)d_in[2];
    const float* bq     = (const float*)d_in[3];
    const float* wk     = (const float*)d_in[4];
    const float* bk     = (const float*)d_in[5];
    const float* wv     = (const float*)d_in[6];
    const float* bv     = (const float*)d_in[7];
    const float* wo     = (const float*)d_in[8];
    const float* bo     = (const float*)d_in[9];
    const float* w1     = (const float*)d_in[10];
    const float* b1     = (const float*)d_in[11];
    const float* w2     = (const float*)d_in[12];
    const float* b2     = (const float*)d_in[13];
    const float* alpha1 = (const float*)d_in[14];
    const float* beta1  = (const float*)d_in[15];
    const float* alpha2 = (const float*)d_in[16];
    const float* beta2  = (const float*)d_in[17];
    float* out = (float*)d_out;

    const int SMEM128 = 3 * (128 * SA2 * 2 + 128 * SA2 * 2);   // 61440
    const int SMEM64  = 3 * (128 * SA2 * 2 + 64 * SA2 * 2);    // 46080
    cudaFuncSetAttribute((const void*)gemm_mma_kernel<1, 0>, cudaFuncAttributeMaxDynamicSharedMemorySize, SMEM128);
    cudaFuncSetAttribute((const void*)gemm_mma_kernel<1, 1>, cudaFuncAttributeMaxDynamicSharedMemorySize, SMEM128);
    cudaFuncSetAttribute((const void*)gemm_mma_kernel<0, 0>, cudaFuncAttributeMaxDynamicSharedMemorySize, SMEM128);
    cudaFuncSetAttribute((const void*)scores_mma_kernel,     cudaFuncAttributeMaxDynamicSharedMemorySize, SMEM128);
    cudaFuncSetAttribute((const void*)ctx_mma_kernel,        cudaFuncAttributeMaxDynamicSharedMemorySize, SMEM64);

    __half *xn, *qkv, *vt, *ctx, *ff, *sc, *wqkvt, *wot, *w1t, *w2t;
    float *x1, *bqkv;
    cudaGetSymbolAddress((void**)&xn,    g_xn);
    cudaGetSymbolAddress((void**)&qkv,   g_qkv);
    cudaGetSymbolAddress((void**)&vt,    g_vt);
    cudaGetSymbolAddress((void**)&ctx,   g_ctx);
    cudaGetSymbolAddress((void**)&x1,    g_x1);
    cudaGetSymbolAddress((void**)&ff,    g_ff);
    cudaGetSymbolAddress((void**)&sc,    g_sc);
    cudaGetSymbolAddress((void**)&wqkvt, g_wqkvt);
    cudaGetSymbolAddress((void**)&wot,   g_wot);
    cudaGetSymbolAddress((void**)&w1t,   g_w1t);
    cudaGetSymbolAddress((void**)&w2t,   g_w2t);
    cudaGetSymbolAddress((void**)&bqkv,  g_bqkv);

    dim3 tb(32, 8);
    // launch 0: all weight transposes fp32 -> fp16 K-major
    wtrans_all_kernel<<<12288, tb>>>(wq, wk, wv, wo, w1, w2, wqkvt, wot, w1t, w2t);
    // launch 1
    bcat_kernel<<<12, 256>>>(bq, bk, bv, bqkv);
    // launch 2: LN1
    ln_kernel<<<ROWS, 256>>>(x, xn, alpha1, beta1);
    // launch 3: fused QKV projection (half out)
    gemm_mma_kernel<1, 0><<<dim3(24, 32), 256, SMEM128>>>(xn, DDM, wqkvt, bqkv,
                                                          nullptr, qkv, QKVLD, DDM);
    // launch 4
    vtrans_kernel<<<dim3(32, 2, BHH), tb>>>(qkv, vt);
    // launch 5 (ncu -s 5 profiles this): scores
    scores_mma_kernel<<<dim3(8, 8, BHH), 256, SMEM128>>>(qkv, mask, sc);
    softmax_kernel<<<BHH * SSZ, 256>>>(sc);
    ctx_mma_kernel<<<dim3(1, 8, BHH), 256, SMEM64>>>(sc, vt, ctx);

    // output projection + residual (float out)
    gemm_mma_kernel<0, 0><<<dim3(8, 32), 256, SMEM128>>>(ctx, DDM, wot, bo,
                                                         x, x1, DDM, DDM);
    // LN2 + FFN + residual
    ln_kernel<<<ROWS, 256>>>(x1, xn, alpha2, beta2);
    gemm_mma_kernel<1, 1><<<dim3(32, 32), 256, SMEM128>>>(xn, DDM, w1t, b1,
                                                          nullptr, ff, DFF, DDM);
    gemm_mma_kernel<0, 0><<<dim3(8, 32), 256, SMEM128>>>(ff, DFF, w2t, b2,
                                                         x1, out, DDM, DFF);
}

// round 6
// speedup vs baseline: 7.2684x; 1.3023x over previous
#include <cuda_runtime.h>
#include <cuda_fp16.h>
#include <cstdint>

// ---------------- problem dims ----------------
#define BBX   4
#define SSZ   1024
#define DDM   1024
#define HHX   16
#define DFF   4096
#define ROWS  4096          // BBX*SSZ
#define BHH   64            // BBX*HHX
#define QKVLD 3072
#define SA2   40            // padded smem stride (halfs) for BK=32 (GEMM)

// flash-attention smem strides (halfs)
#define LDQ   72
#define LDK   72
#define LDV   136
#define QSZ   (128 * LDQ)       // 9216 halfs
#define KSZ   (128 * LDK)       // 9216 halfs
#define VSZ   (64 * LDV)        // 8704 halfs
#define FL_SMEM (2 * (QSZ + 2 * KSZ + 2 * VSZ) + 4096)   // 94208 bytes

// ---------------- scratch (static device globals) ----------------
__device__ __half g_xn   [(size_t)ROWS * DDM];
__device__ __half g_qkv  [(size_t)ROWS * QKVLD];
__device__ __half g_vt   [(size_t)BHH * 64 * SSZ];
__device__ __half g_ctx  [(size_t)ROWS * DDM];
__device__ float  g_x1   [(size_t)ROWS * DDM];
__device__ __half g_ff   [(size_t)ROWS * DFF];
__device__ __half g_wqkvt[(size_t)QKVLD * DDM];
__device__ __half g_wot  [(size_t)DDM * DDM];
__device__ __half g_w1t  [(size_t)DFF * DDM];
__device__ __half g_w2t  [(size_t)DDM * DFF];
__device__ float  g_bqkv [QKVLD];

// ---------------- helpers ----------------
__device__ __forceinline__ uint32_t smem_u32(const void* p) {
    uint32_t a;
    asm("{ .reg .u64 t; cvta.to.shared.u64 t, %1; cvt.u32.u64 %0, t; }"
        : "=r"(a) : "l"(p));
    return a;
}
__device__ __forceinline__ void cpasync16(uint32_t s, const void* g) {
    asm volatile("cp.async.cg.shared.global [%0], [%1], 16;" :: "r"(s), "l"(g));
}
#define CP_COMMIT() asm volatile("cp.async.commit_group;" ::: "memory")
#define CP_WAIT1()  asm volatile("cp.async.wait_group 1;" ::: "memory")
#define CP_WAIT0()  asm volatile("cp.async.wait_group 0;" ::: "memory")

__device__ __forceinline__ void ldsm4(uint32_t addr, uint32_t& r0, uint32_t& r1,
                                      uint32_t& r2, uint32_t& r3) {
    asm volatile("ldmatrix.sync.aligned.m8n8.x4.shared.b16 {%0,%1,%2,%3}, [%4];"
                 : "=r"(r0), "=r"(r1), "=r"(r2), "=r"(r3) : "r"(addr));
}

__device__ __forceinline__ void mma_f16(float (&d)[4],
                                        const uint32_t (&a)[4],
                                        const uint32_t (&b)[2]) {
    asm volatile(
        "mma.sync.aligned.m16n8k16.row.col.f32.f16.f16.f32 "
        "{%0,%1,%2,%3},{%4,%5,%6,%7},{%8,%9},{%0,%1,%2,%3};"
        : "+f"(d[0]), "+f"(d[1]), "+f"(d[2]), "+f"(d[3])
        : "r"(a[0]), "r"(a[1]), "r"(a[2]), "r"(a[3]),
          "r"(b[0]), "r"(b[1]));
}

// ---------------- GEMM: cp.async tile loader (one BK=32 chunk) ----------------
template <int NI>
__device__ __forceinline__ void load_chunk(const __half* __restrict__ A, int lda,
                                           const __half* __restrict__ B, int ldb,
                                           int k0, uint32_t sA, uint32_t sB, int tid)
{
    #pragma unroll
    for (int it = 0; it < 2; it++) {
        const int idx = tid + it * 256;
        const int r = idx >> 2, c = idx & 3;
        cpasync16(sA + (uint32_t)(r * SA2 + c * 8) * 2,
                  A + (size_t)r * lda + k0 + c * 8);
    }
    #pragma unroll
    for (int it = 0; it < (NI * 32 * 4) / 256; it++) {
        const int idx = tid + it * 256;
        const int n = idx >> 2, c = idx & 3;
        cpasync16(sB + (uint32_t)(n * SA2 + c * 8) * 2,
                  B + (size_t)n * ldb + k0 + c * 8);
    }
}

// ---------------- GEMM mainloop (ldmatrix fragments) ----------------
template <int NI>
__device__ __forceinline__ void mma_mainloop(const __half* __restrict__ A, int lda,
                                             const __half* __restrict__ B, int ldb,
                                             int K, float (&acc)[4][NI][4], char* dyn)
{
    constexpr int ASZ = 128 * SA2 * 2;
    constexpr int BSZ = NI * 32 * SA2 * 2;
    constexpr int STG = ASZ + BSZ;
    const int tid = threadIdx.x;
    const int wid = tid >> 5, lane = tid & 31;
    const int wm = wid >> 2, wn = wid & 3;
    const uint32_t sbase = smem_u32(dyn);

    const int a_row = wm * 64 + (lane & 15);
    const int a_col = (lane >> 4) << 3;
    const uint32_t aOff = (uint32_t)(a_row * SA2 + a_col) * 2;
    const int b_row = wn * (NI * 8) + (lane & 7) + ((lane >> 4) << 3);
    const int b_col = ((lane >> 3) & 1) << 3;
    const uint32_t bOff = (uint32_t)(b_row * SA2 + b_col) * 2;

    const int nk = K >> 5;
    #pragma unroll
    for (int s = 0; s < 2; s++) {
        if (s < nk)
            load_chunk<NI>(A, lda, B, ldb, s * 32,
                           sbase + s * STG, sbase + s * STG + ASZ, tid);
        CP_COMMIT();
    }

    for (int c = 0; c < nk; c++) {
        CP_WAIT1();
        __syncthreads();
        const int nst = c + 2;
        if (nst < nk) {
            const int s2 = nst % 3;
            load_chunk<NI>(A, lda, B, ldb, nst * 32,
                           sbase + s2 * STG, sbase + s2 * STG + ASZ, tid);
        }
        CP_COMMIT();

        const int s = c % 3;
        const uint32_t aBase = sbase + s * STG + aOff;
        const uint32_t bBase = sbase + s * STG + ASZ + bOff;

        #pragma unroll
        for (int ks = 0; ks < 2; ks++) {
            const uint32_t kb = (uint32_t)(ks * 16) * 2;
            uint32_t afr[4][4];
            #pragma unroll
            for (int mi = 0; mi < 4; mi++)
                ldsm4(aBase + kb + (uint32_t)(mi * 16 * SA2) * 2,
                      afr[mi][0], afr[mi][1], afr[mi][2], afr[mi][3]);
            uint32_t bfr[NI][2];
            #pragma unroll
            for (int np = 0; np < NI / 2; np++)
                ldsm4(bBase + kb + (uint32_t)(np * 16 * SA2) * 2,
                      bfr[2 * np][0], bfr[2 * np][1],
                      bfr[2 * np + 1][0], bfr[2 * np + 1][1]);
            #pragma unroll
            for (int mi = 0; mi < 4; mi++)
                #pragma unroll
                for (int ni = 0; ni < NI; ni++)
                    mma_f16(acc[mi][ni], afr[mi], bfr[ni]);
        }
    }
}

// ---------------- dense GEMM: C = A.Bt^T + bias (+relu) (+res) ---------
template <int OUT_HALF, int RELU>
__global__ __launch_bounds__(256, 2) void gemm_mma_kernel(
    const __half* __restrict__ A, int lda,
    const __half* __restrict__ Bt,
    const float* __restrict__ bias, const float* __restrict__ res,
    void* __restrict__ Cv, int ldc, int K)
{
    extern __shared__ char dyn[];
    const int mBase = blockIdx.y * 128;
    const int nBase = blockIdx.x * 128;
    const __half* Ab = A + (size_t)mBase * lda;
    const __half* Bb = Bt + (size_t)nBase * K;

    float acc[4][4][4];
    #pragma unroll
    for (int i = 0; i < 4; i++)
        #pragma unroll
        for (int j = 0; j < 4; j++)
            #pragma unroll
            for (int q = 0; q < 4; q++) acc[i][j][q] = 0.f;

    mma_mainloop<4>(Ab, lda, Bb, K, K, acc, dyn);

    const int wid = threadIdx.x >> 5, lane = threadIdx.x & 31;
    const int wm = wid >> 2, wn = wid & 3;
    const int gid = lane >> 2, tig = lane & 3;
    const int mW = mBase + wm * 64;
    const int nW = nBase + wn * 32;

    #pragma unroll
    for (int mi = 0; mi < 4; mi++) {
        #pragma unroll
        for (int half_ = 0; half_ < 2; half_++) {
            const int row = mW + mi * 16 + gid + half_ * 8;
            #pragma unroll
            for (int ni = 0; ni < 4; ni++) {
                const int col = nW + ni * 8 + tig * 2;
                float v0 = acc[mi][ni][half_ * 2 + 0] + bias[col];
                float v1 = acc[mi][ni][half_ * 2 + 1] + bias[col + 1];
                if (RELU) { v0 = fmaxf(v0, 0.f); v1 = fmaxf(v1, 0.f); }
                if (OUT_HALF) {
                    __half* cRow = (__half*)Cv + (size_t)row * ldc;
                    *reinterpret_cast<__half2*>(cRow + col) = __floats2half2_rn(v0, v1);
                } else {
                    float* cRow = (float*)Cv + (size_t)row * ldc;
                    if (res) {
                        const float* rRow = res + (size_t)row * ldc;
                        v0 += rRow[col]; v1 += rRow[col + 1];
                    }
                    *reinterpret_cast<float2*>(cRow + col) = make_float2(v0, v1);
                }
            }
        }
    }
}

// ---------------- fused flash attention ---------------------------------
// grid (8 m-tiles, 64 bh); 256 threads = 8 warps; warp owns 16 rows x all 128 kv cols.
// smem: Q[128x64 +pad] | K[2][128x64 +pad] | V^T[2][64x128 +pad] | maskAdd[1024]f
__global__ __launch_bounds__(256) void flash_kernel(
    const __half* __restrict__ qkv, const __half* __restrict__ vt,
    const int* __restrict__ mask, __half* __restrict__ ctx)
{
    extern __shared__ char dyn[];
    const uint32_t sb = smem_u32(dyn);
    float* sMask = (float*)(dyn + 2 * (QSZ + 2 * KSZ + 2 * VSZ));

    const int bh = blockIdx.y, b = bh >> 4, h = bh & 15;
    const int mBase = blockIdx.x * 128;
    const int tid = threadIdx.x, wid = tid >> 5, lane = tid & 31;
    const int gid = lane >> 2, tig = lane & 3;

    // additive mask values (0 or -60000)
    #pragma unroll
    for (int it = 0; it < 4; it++) {
        const int i = tid + it * 256;
        sMask[i] = (mask[b * SSZ + i] == 0) ? -60000.f : 0.f;
    }

    // Q tile load (128 x 64 halfs)
    {
        const __half* Qg = qkv + (size_t)(b * SSZ + mBase) * QKVLD + h * 64;
        #pragma unroll
        for (int it = 0; it < 4; it++) {
            const int idx = tid + it * 256;
            const int r = idx >> 3, c = idx & 7;
            cpasync16(sb + (uint32_t)(r * LDQ + c * 8) * 2,
                      Qg + (size_t)r * QKVLD + c * 8);
        }
    }
    // K/V loaders
    const __half* Kg0 = qkv + (size_t)(b * SSZ) * QKVLD + 1024 + h * 64;
    const __half* Vg0 = vt + (size_t)bh * 64 * SSZ;
    auto load_kv = [&](int stage, int t) {
        const __half* Kg = Kg0 + (size_t)(t * 128) * QKVLD;
        const uint32_t kS = sb + (uint32_t)((QSZ + stage * KSZ) * 2);
        #pragma unroll
        for (int it = 0; it < 4; it++) {
            const int idx = tid + it * 256;
            const int r = idx >> 3, c = idx & 7;
            cpasync16(kS + (uint32_t)(r * LDK + c * 8) * 2,
                      Kg + (size_t)r * QKVLD + c * 8);
        }
        const __half* Vg = Vg0 + t * 128;
        const uint32_t vS = sb + (uint32_t)((QSZ + 2 * KSZ + stage * VSZ) * 2);
        #pragma unroll
        for (int it = 0; it < 4; it++) {
            const int idx = tid + it * 256;
            const int r = idx >> 4, c = idx & 15;
            cpasync16(vS + (uint32_t)(r * LDV + c * 8) * 2,
                      Vg + (size_t)r * SSZ + c * 8);
        }
    };
    load_kv(0, 0);
    CP_COMMIT();

    // ldmatrix lane offsets
    const uint32_t aOffQ = (uint32_t)(((wid * 16 + (lane & 15)) * LDQ + ((lane >> 4) << 3)) * 2);
    const uint32_t bOffK = (uint32_t)((((lane & 7) + ((lane >> 4) << 3)) * LDK + (((lane >> 3) & 1) << 3)) * 2);
    const uint32_t bOffV = (uint32_t)((((lane & 7) + ((lane >> 4) << 3)) * LDV + (((lane >> 3) & 1) << 3)) * 2);

    uint32_t qf[4][4];
    float oacc[8][4];
    #pragma unroll
    for (int i = 0; i < 8; i++)
        #pragma unroll
        for (int q = 0; q < 4; q++) oacc[i][q] = 0.f;
    float m0 = -1e30f, m1 = -1e30f, l0 = 0.f, l1 = 0.f;

    for (int t = 0; t < 8; t++) {
        __syncthreads();                     // prev compute done (buffers reusable)
        if (t < 7) { load_kv((t + 1) & 1, t + 1); CP_COMMIT(); CP_WAIT1(); }
        else       { CP_WAIT0(); }
        __syncthreads();                     // data for tile t ready

        if (t == 0) {
            #pragma unroll
            for (int ks = 0; ks < 4; ks++)
                ldsm4(sb + aOffQ + ks * 32,
                      qf[ks][0], qf[ks][1], qf[ks][2], qf[ks][3]);
        }

        // ---- S = Q K^T (16 rows x 128 cols per warp) ----
        float sacc[16][4];
        #pragma unroll
        for (int ni = 0; ni < 16; ni++)
            #pragma unroll
            for (int q = 0; q < 4; q++) sacc[ni][q] = 0.f;

        const uint32_t kb = sb + (uint32_t)((QSZ + (t & 1) * KSZ) * 2) + bOffK;
        #pragma unroll
        for (int ks = 0; ks < 4; ks++) {
            uint32_t bfr[16][2];
            #pragma unroll
            for (int np = 0; np < 8; np++)
                ldsm4(kb + ks * 32 + (uint32_t)(np * 16 * LDK) * 2,
                      bfr[2 * np][0], bfr[2 * np][1],
                      bfr[2 * np + 1][0], bfr[2 * np + 1][1]);
            #pragma unroll
            for (int ni = 0; ni < 16; ni++)
                mma_f16(sacc[ni], qf[ks], bfr[ni]);
        }

        // ---- scale + mask + online softmax ----
        float tm0 = -1e30f, tm1 = -1e30f;
        #pragma unroll
        for (int ni = 0; ni < 16; ni++) {
            const int colb = t * 128 + ni * 8 + 2 * tig;
            const float ma = sMask[colb], mb = sMask[colb + 1];
            sacc[ni][0] = sacc[ni][0] * 0.125f + ma;
            sacc[ni][1] = sacc[ni][1] * 0.125f + mb;
            sacc[ni][2] = sacc[ni][2] * 0.125f + ma;
            sacc[ni][3] = sacc[ni][3] * 0.125f + mb;
            tm0 = fmaxf(tm0, fmaxf(sacc[ni][0], sacc[ni][1]));
            tm1 = fmaxf(tm1, fmaxf(sacc[ni][2], sacc[ni][3]));
        }
        tm0 = fmaxf(tm0, __shfl_xor_sync(0xffffffffu, tm0, 1));
        tm0 = fmaxf(tm0, __shfl_xor_sync(0xffffffffu, tm0, 2));
        tm1 = fmaxf(tm1, __shfl_xor_sync(0xffffffffu, tm1, 1));
        tm1 = fmaxf(tm1, __shfl_xor_sync(0xffffffffu, tm1, 2));

        const float mn0 = fmaxf(m0, tm0), mn1 = fmaxf(m1, tm1);
        const float c0 = __expf(m0 - mn0), c1 = __expf(m1 - mn1);
        m0 = mn0; m1 = mn1;

        float ls0 = 0.f, ls1 = 0.f;
        #pragma unroll
        for (int ni = 0; ni < 16; ni++) {
            sacc[ni][0] = __expf(sacc[ni][0] - m0);
            sacc[ni][1] = __expf(sacc[ni][1] - m0);
            sacc[ni][2] = __expf(sacc[ni][2] - m1);
            sacc[ni][3] = __expf(sacc[ni][3] - m1);
            ls0 += sacc[ni][0] + sacc[ni][1];
            ls1 += sacc[ni][2] + sacc[ni][3];
        }
        l0 = l0 * c0 + ls0;
        l1 = l1 * c1 + ls1;
        #pragma unroll
        for (int ni = 0; ni < 8; ni++) {
            oacc[ni][0] *= c0; oacc[ni][1] *= c0;
            oacc[ni][2] *= c1; oacc[ni][3] *= c1;
        }

        // ---- O += P V  (P fragments come straight from sacc registers) ----
        const uint32_t vb = sb + (uint32_t)((QSZ + 2 * KSZ + (t & 1) * VSZ) * 2) + bOffV;
        #pragma unroll
        for (int j = 0; j < 8; j++) {
            uint32_t pf[4];
            {
                __half2 p0 = __floats2half2_rn(sacc[2 * j][0],     sacc[2 * j][1]);
                __half2 p1 = __floats2half2_rn(sacc[2 * j][2],     sacc[2 * j][3]);
                __half2 p2 = __floats2half2_rn(sacc[2 * j + 1][0], sacc[2 * j + 1][1]);
                __half2 p3 = __floats2half2_rn(sacc[2 * j + 1][2], sacc[2 * j + 1][3]);
                pf[0] = *reinterpret_cast<uint32_t*>(&p0);
                pf[1] = *reinterpret_cast<uint32_t*>(&p1);
                pf[2] = *reinterpret_cast<uint32_t*>(&p2);
                pf[3] = *reinterpret_cast<uint32_t*>(&p3);
            }
            uint32_t bfr2[8][2];
            #pragma unroll
            for (int np = 0; np < 4; np++)
                ldsm4(vb + j * 32 + (uint32_t)(np * 16 * LDV) * 2,
                      bfr2[2 * np][0], bfr2[2 * np][1],
                      bfr2[2 * np + 1][0], bfr2[2 * np + 1][1]);
            #pragma unroll
            for (int ni = 0; ni < 8; ni++)
                mma_f16(oacc[ni], pf, bfr2[ni]);
        }
    }

    // finalize: reduce row sums across the quad, divide, write
    l0 += __shfl_xor_sync(0xffffffffu, l0, 1);
    l0 += __shfl_xor_sync(0xffffffffu, l0, 2);
    l1 += __shfl_xor_sync(0xffffffffu, l1, 1);
    l1 += __shfl_xor_sync(0xffffffffu, l1, 2);
    const float inv0 = 1.f / l0, inv1 = 1.f / l1;

    const int row0 = mBase + wid * 16 + gid;
    __half* o0 = ctx + (size_t)(b * SSZ + row0) * DDM + h * 64;
    __half* o1 = o0 + 8 * DDM;
    #pragma unroll
    for (int ni = 0; ni < 8; ni++) {
        const int col = ni * 8 + 2 * tig;
        *reinterpret_cast<__half2*>(o0 + col) =
            __floats2half2_rn(oacc[ni][0] * inv0, oacc[ni][1] * inv0);
        *reinterpret_cast<__half2*>(o1 + col) =
            __floats2half2_rn(oacc[ni][2] * inv1, oacc[ni][3] * inv1);
    }
}

// ---------------- LayerNorm (ddof=1, eps on std, scalar a/b), half out --
__global__ __launch_bounds__(256) void ln_kernel(const float* __restrict__ x,
                                                 __half* __restrict__ y,
                                                 const float* __restrict__ alpha,
                                                 const float* __restrict__ beta)
{
    __shared__ float red[256];
    const int row = blockIdx.x, tid = threadIdx.x;
    const float* xr = x + (size_t)row * DDM;
    __half* yr = y + (size_t)row * DDM;

    float4 v = reinterpret_cast<const float4*>(xr)[tid];
    red[tid] = v.x + v.y + v.z + v.w; __syncthreads();
    for (int o = 128; o > 0; o >>= 1) { if (tid < o) red[tid] += red[tid + o]; __syncthreads(); }
    const float mean = red[0] * (1.0f / DDM);
    __syncthreads();

    float4 d = make_float4(v.x - mean, v.y - mean, v.z - mean, v.w - mean);
    red[tid] = d.x * d.x + d.y * d.y + d.z * d.z + d.w * d.w; __syncthreads();
    for (int o = 128; o > 0; o >>= 1) { if (tid < o) red[tid] += red[tid + o]; __syncthreads(); }
    const float stdv = sqrtf(red[0] * (1.0f / (DDM - 1)));
    const float a = alpha[0], bta = beta[0];
    const float inv = a / (stdv + 1e-6f);

    __half2 o0 = __floats2half2_rn(d.x * inv + bta, d.y * inv + bta);
    __half2 o1 = __floats2half2_rn(d.z * inv + bta, d.w * inv + bta);
    uint2 pk;
    pk.x = *reinterpret_cast<uint32_t*>(&o0);
    pk.y = *reinterpret_cast<uint32_t*>(&o1);
    reinterpret_cast<uint2*>(yr)[tid] = pk;
}

// ---------------- merged weight transpose (all 6 matrices, 1 launch) -----
__global__ void wtrans_all_kernel(const float* __restrict__ wq, const float* __restrict__ wk,
                                  const float* __restrict__ wv, const float* __restrict__ wo,
                                  const float* __restrict__ w1, const float* __restrict__ w2,
                                  __half* __restrict__ wqkvt, __half* __restrict__ wot,
                                  __half* __restrict__ w1t,   __half* __restrict__ w2t)
{
    __shared__ float t[32][33];
    int tIdx = blockIdx.x;
    const float* src; __half* dst; int R, C;
    if (tIdx < 3072) {
        const int m = tIdx >> 10;
        src = (m == 0) ? wq : (m == 1) ? wk : wv;
        dst = wqkvt + (size_t)m * 1024 * 1024;
        R = 1024; C = 1024; tIdx &= 1023;
    } else if (tIdx < 4096) {
        src = wo; dst = wot; R = 1024; C = 1024; tIdx -= 3072;
    } else if (tIdx < 8192) {
        src = w1; dst = w1t; R = 1024; C = 4096; tIdx -= 4096;
    } else {
        src = w2; dst = w2t; R = 4096; C = 1024; tIdx -= 8192;
    }
    const int nCx = C >> 5;
    const int c0 = (tIdx % nCx) * 32, r0 = (tIdx / nCx) * 32;
    const int tx = threadIdx.x, ty = threadIdx.y;
    #pragma unroll
    for (int i = ty; i < 32; i += 8)
        t[i][tx] = src[(size_t)(r0 + i) * C + c0 + tx];
    __syncthreads();
    #pragma unroll
    for (int i = ty; i < 32; i += 8)
        dst[(size_t)(c0 + i) * R + r0 + tx] = __float2half_rn(t[tx][i]);
}

__global__ void vtrans_kernel(const __half* __restrict__ qkv, __half* __restrict__ vt)
{
    __shared__ __half t[32][34];
    const int bh = blockIdx.z, b = bh >> 4, h = bh & 15;
    const int s0 = blockIdx.x * 32, d0 = blockIdx.y * 32;
    const int tx = threadIdx.x, ty = threadIdx.y;
    #pragma unroll
    for (int i = ty; i < 32; i += 8)
        t[i][tx] = qkv[(size_t)(b * SSZ + s0 + i) * QKVLD + 2048 + h * 64 + d0 + tx];
    __syncthreads();
    #pragma unroll
    for (int i = ty; i < 32; i += 8)
        vt[(size_t)bh * 64 * SSZ + (size_t)(d0 + i) * SSZ + s0 + tx] = t[tx][i];
}

__global__ void bcat_kernel(const float* __restrict__ bq, const float* __restrict__ bk,
                            const float* __restrict__ bv, float* __restrict__ dst)
{
    const int i = blockIdx.x * 256 + threadIdx.x;
    if (i < 1024) dst[i] = bq[i];
    else if (i < 2048) dst[i] = bk[i - 1024];
    else dst[i] = bv[i - 2048];
}

// ---------------- launch ----------------
extern "C" void kernel_launch(void* const* d_in, const int* in_sizes, int n_in,
                              void* d_out, int out_size)
{
    const float* x      = (const float*)d_in[0];
    const int*   mask   = (const int*)  d_in[1];
    const float* wq     = (const float*)d_in[2];
    const float* bq     = (const float*)d_in[3];
    const float* wk     = (const float*)d_in[4];
    const float* bk     = (const float*)d_in[5];
    const float* wv     = (const float*)d_in[6];
    const float* bv     = (const float*)d_in[7];
    const float* wo     = (const float*)d_in[8];
    const float* bo     = (const float*)d_in[9];
    const float* w1     = (const float*)d_in[10];
    const float* b1     = (const float*)d_in[11];
    const float* w2     = (const float*)d_in[12];
    const float* b2     = (const float*)d_in[13];
    const float* alpha1 = (const float*)d_in[14];
    const float* beta1  = (const float*)d_in[15];
    const float* alpha2 = (const float*)d_in[16];
    const float* beta2  = (const float*)d_in[17];
    float* out = (float*)d_out;

    const int SMEM128 = 3 * (128 * SA2 * 2 + 128 * SA2 * 2);   // 61440
    cudaFuncSetAttribute((const void*)gemm_mma_kernel<1, 0>, cudaFuncAttributeMaxDynamicSharedMemorySize, SMEM128);
    cudaFuncSetAttribute((const void*)gemm_mma_kernel<1, 1>, cudaFuncAttributeMaxDynamicSharedMemorySize, SMEM128);
    cudaFuncSetAttribute((const void*)gemm_mma_kernel<0, 0>, cudaFuncAttributeMaxDynamicSharedMemorySize, SMEM128);
    cudaFuncSetAttribute((const void*)flash_kernel,          cudaFuncAttributeMaxDynamicSharedMemorySize, FL_SMEM);

    __half *xn, *qkv, *vt, *ctx, *ff, *wqkvt, *wot, *w1t, *w2t;
    float *x1, *bqkv;
    cudaGetSymbolAddress((void**)&xn,    g_xn);
    cudaGetSymbolAddress((void**)&qkv,   g_qkv);
    cudaGetSymbolAddress((void**)&vt,    g_vt);
    cudaGetSymbolAddress((void**)&ctx,   g_ctx);
    cudaGetSymbolAddress((void**)&x1,    g_x1);
    cudaGetSymbolAddress((void**)&ff,    g_ff);
    cudaGetSymbolAddress((void**)&wqkvt, g_wqkvt);
    cudaGetSymbolAddress((void**)&wot,   g_wot);
    cudaGetSymbolAddress((void**)&w1t,   g_w1t);
    cudaGetSymbolAddress((void**)&w2t,   g_w2t);
    cudaGetSymbolAddress((void**)&bqkv,  g_bqkv);

    dim3 tb(32, 8);
    // 0: all weight transposes fp32 -> fp16 K-major
    wtrans_all_kernel<<<12288, tb>>>(wq, wk, wv, wo, w1, w2, wqkvt, wot, w1t, w2t);
    // 1: bias concat
    bcat_kernel<<<12, 256>>>(bq, bk, bv, bqkv);
    // 2: LN1
    ln_kernel<<<ROWS, 256>>>(x, xn, alpha1, beta1);
    // 3: fused QKV projection (half out)
    gemm_mma_kernel<1, 0><<<dim3(24, 32), 256, SMEM128>>>(xn, DDM, wqkvt, bqkv,
                                                          nullptr, qkv, QKVLD, DDM);
    // 4: V transpose to [bh][d][s]
    vtrans_kernel<<<dim3(32, 2, BHH), tb>>>(qkv, vt);
    // 5: fused flash attention (ncu -s 5 profiles this)
    flash_kernel<<<dim3(8, BHH), 256, FL_SMEM>>>(qkv, vt, mask, ctx);
    // 6: output projection + residual (float out)
    gemm_mma_kernel<0, 0><<<dim3(8, 32), 256, SMEM128>>>(ctx, DDM, wot, bo,
                                                         x, x1, DDM, DDM);
    // 7: LN2
    ln_kernel<<<ROWS, 256>>>(x1, xn, alpha2, beta2);
    // 8: FF1 (relu, half out)
    gemm_mma_kernel<1, 1><<<dim3(32, 32), 256, SMEM128>>>(xn, DDM, w1t, b1,
                                                          nullptr, ff, DFF, DDM);
    // 9: FF2 + residual (float out)
    gemm_mma_kernel<0, 0><<<dim3(8, 32), 256, SMEM128>>>(ff, DFF, w2t, b2,
                                                         x1, out, DDM, DFF);
}

// round 7
// speedup vs baseline: 8.1467x; 1.1208x over previous
#include <cuda_runtime.h>
#include <cuda_fp16.h>
#include <cstdint>

// ---------------- problem dims ----------------
#define BBX   4
#define SSZ   1024
#define DDM   1024
#define HHX   16
#define DFF   4096
#define ROWS  4096          // BBX*SSZ
#define BHH   64            // BBX*HHX
#define QKVLD 3072
#define SA2   40            // padded smem stride (halfs) for BK=32 (GEMM)

// flash-attention smem strides (halfs)
#define LDQ   72
#define LDK   72
#define LDV   136
#define QSZ   (128 * LDQ)       // 9216 halfs
#define KSZ   (128 * LDK)       // 9216 halfs
#define VSZ   (64 * LDV)        // 8704 halfs
#define FL_SMEM (2 * (QSZ + 2 * KSZ + 2 * VSZ) + 4096)   // 94208 bytes

// ---------------- scratch (static device globals) ----------------
__device__ __half g_xn   [(size_t)ROWS * DDM];
__device__ __half g_qkv  [(size_t)ROWS * QKVLD];
__device__ __half g_vt   [(size_t)BHH * 64 * SSZ];
__device__ __half g_ctx  [(size_t)ROWS * DDM];
__device__ float  g_x1   [(size_t)ROWS * DDM];
__device__ __half g_ff   [(size_t)ROWS * DFF];
__device__ __half g_wqkvt[(size_t)QKVLD * DDM];
__device__ __half g_wot  [(size_t)DDM * DDM];
__device__ __half g_w1t  [(size_t)DFF * DDM];
__device__ __half g_w2t  [(size_t)DDM * DFF];
__device__ float  g_bqkv [QKVLD];

// ---------------- helpers ----------------
__device__ __forceinline__ uint32_t smem_u32(const void* p) {
    uint32_t a;
    asm("{ .reg .u64 t; cvta.to.shared.u64 t, %1; cvt.u32.u64 %0, t; }"
        : "=r"(a) : "l"(p));
    return a;
}
__device__ __forceinline__ void cpasync16(uint32_t s, const void* g) {
    asm volatile("cp.async.cg.shared.global [%0], [%1], 16;" :: "r"(s), "l"(g));
}
#define CP_COMMIT() asm volatile("cp.async.commit_group;" ::: "memory")
#define CP_WAIT1()  asm volatile("cp.async.wait_group 1;" ::: "memory")
#define CP_WAIT0()  asm volatile("cp.async.wait_group 0;" ::: "memory")

__device__ __forceinline__ void ldsm4(uint32_t addr, uint32_t& r0, uint32_t& r1,
                                      uint32_t& r2, uint32_t& r3) {
    asm volatile("ldmatrix.sync.aligned.m8n8.x4.shared.b16 {%0,%1,%2,%3}, [%4];"
                 : "=r"(r0), "=r"(r1), "=r"(r2), "=r"(r3) : "r"(addr));
}

__device__ __forceinline__ void mma_f16(float (&d)[4],
                                        const uint32_t (&a)[4],
                                        const uint32_t (&b)[2]) {
    asm volatile(
        "mma.sync.aligned.m16n8k16.row.col.f32.f16.f16.f32 "
        "{%0,%1,%2,%3},{%4,%5,%6,%7},{%8,%9},{%0,%1,%2,%3};"
        : "+f"(d[0]), "+f"(d[1]), "+f"(d[2]), "+f"(d[3])
        : "r"(a[0]), "r"(a[1]), "r"(a[2]), "r"(a[3]),
          "r"(b[0]), "r"(b[1]));
}

// ---------------- GEMM: cp.async tile loader (one BK=32 chunk) ----------------
template <int NI>
__device__ __forceinline__ void load_chunk(const __half* __restrict__ A, int lda,
                                           const __half* __restrict__ B, int ldb,
                                           int k0, uint32_t sA, uint32_t sB, int tid)
{
    #pragma unroll
    for (int it = 0; it < 2; it++) {
        const int idx = tid + it * 256;
        const int r = idx >> 2, c = idx & 3;
        cpasync16(sA + (uint32_t)(r * SA2 + c * 8) * 2,
                  A + (size_t)r * lda + k0 + c * 8);
    }
    #pragma unroll
    for (int it = 0; it < (NI * 32 * 4) / 256; it++) {
        const int idx = tid + it * 256;
        const int n = idx >> 2, c = idx & 3;
        cpasync16(sB + (uint32_t)(n * SA2 + c * 8) * 2,
                  B + (size_t)n * ldb + k0 + c * 8);
    }
}

// ---------------- GEMM mainloop (double-buffered ldmatrix fragments) ----
// block tile 128 x (NI*32); 8 warps (2 m x 4 n), warp tile 64x(NI*8)
template <int NI>
__device__ __forceinline__ void mma_mainloop(const __half* __restrict__ A, int lda,
                                             const __half* __restrict__ B, int ldb,
                                             int K, float (&acc)[4][NI][4], char* dyn)
{
    constexpr int ASZ = 128 * SA2 * 2;
    constexpr int BSZ = NI * 32 * SA2 * 2;
    constexpr int STG = ASZ + BSZ;
    const int tid = threadIdx.x;
    const int wid = tid >> 5, lane = tid & 31;
    const int wm = wid >> 2, wn = wid & 3;
    const uint32_t sbase = smem_u32(dyn);

    const int a_row = wm * 64 + (lane & 15);
    const int a_col = (lane >> 4) << 3;
    const uint32_t aOff = (uint32_t)(a_row * SA2 + a_col) * 2;
    const int b_row = wn * (NI * 8) + (lane & 7) + ((lane >> 4) << 3);
    const int b_col = ((lane >> 3) & 1) << 3;
    const uint32_t bOff = (uint32_t)(b_row * SA2 + b_col) * 2;

    const int nk = K >> 5;
    load_chunk<NI>(A, lda, B, ldb, 0, sbase, sbase + ASZ, tid);
    CP_COMMIT();
    if (nk > 1)
        load_chunk<NI>(A, lda, B, ldb, 32, sbase + STG, sbase + STG + ASZ, tid);
    CP_COMMIT();
    CP_WAIT1();
    __syncthreads();

    uint32_t af0[4][4], bf0[NI][2], af1[4][4], bf1[NI][2];
    // prologue: fragments (chunk 0, kstep 0)
    {
        const uint32_t aB = sbase + aOff;
        const uint32_t bB = sbase + ASZ + bOff;
        #pragma unroll
        for (int mi = 0; mi < 4; mi++)
            ldsm4(aB + (uint32_t)(mi * 16 * SA2) * 2,
                  af0[mi][0], af0[mi][1], af0[mi][2], af0[mi][3]);
        #pragma unroll
        for (int np = 0; np < NI / 2; np++)
            ldsm4(bB + (uint32_t)(np * 16 * SA2) * 2,
                  bf0[2 * np][0], bf0[2 * np][1],
                  bf0[2 * np + 1][0], bf0[2 * np + 1][1]);
    }

    for (int c = 0; c < nk; c++) {
        const int s = c % 3;
        if (c + 2 < nk) {
            const int s2 = (c + 2) % 3;
            load_chunk<NI>(A, lda, B, ldb, (c + 2) * 32,
                           sbase + s2 * STG, sbase + s2 * STG + ASZ, tid);
        }
        CP_COMMIT();

        // load kstep-1 fragments of chunk c (independent of ks0 MMAs below)
        {
            const uint32_t aB = sbase + s * STG + aOff + 32;
            const uint32_t bB = sbase + s * STG + ASZ + bOff + 32;
            #pragma unroll
            for (int mi = 0; mi < 4; mi++)
                ldsm4(aB + (uint32_t)(mi * 16 * SA2) * 2,
                      af1[mi][0], af1[mi][1], af1[mi][2], af1[mi][3]);
            #pragma unroll
            for (int np = 0; np < NI / 2; np++)
                ldsm4(bB + (uint32_t)(np * 16 * SA2) * 2,
                      bf1[2 * np][0], bf1[2 * np][1],
                      bf1[2 * np + 1][0], bf1[2 * np + 1][1]);
        }
        // MMA kstep 0
        #pragma unroll
        for (int mi = 0; mi < 4; mi++)
            #pragma unroll
            for (int ni = 0; ni < NI; ni++)
                mma_f16(acc[mi][ni], af0[mi], bf0[ni]);

        if (c + 1 < nk) {
            CP_WAIT1();
            __syncthreads();
            const int s1 = (c + 1) % 3;
            const uint32_t aB = sbase + s1 * STG + aOff;
            const uint32_t bB = sbase + s1 * STG + ASZ + bOff;
            #pragma unroll
            for (int mi = 0; mi < 4; mi++)
                ldsm4(aB + (uint32_t)(mi * 16 * SA2) * 2,
                      af0[mi][0], af0[mi][1], af0[mi][2], af0[mi][3]);
            #pragma unroll
            for (int np = 0; np < NI / 2; np++)
                ldsm4(bB + (uint32_t)(np * 16 * SA2) * 2,
                      bf0[2 * np][0], bf0[2 * np][1],
                      bf0[2 * np + 1][0], bf0[2 * np + 1][1]);
        }
        // MMA kstep 1
        #pragma unroll
        for (int mi = 0; mi < 4; mi++)
            #pragma unroll
            for (int ni = 0; ni < NI; ni++)
                mma_f16(acc[mi][ni], af1[mi], bf1[ni]);
    }
}

// ---------------- dense GEMM: C = A.Bt^T + bias (+relu) (+res) ---------
template <int OUT_HALF, int RELU>
__global__ __launch_bounds__(256, 2) void gemm_mma_kernel(
    const __half* __restrict__ A, int lda,
    const __half* __restrict__ Bt,
    const float* __restrict__ bias, const float* __restrict__ res,
    void* __restrict__ Cv, int ldc, int K)
{
    extern __shared__ char dyn[];
    const int mBase = blockIdx.y * 128;
    const int nBase = blockIdx.x * 128;
    const __half* Ab = A + (size_t)mBase * lda;
    const __half* Bb = Bt + (size_t)nBase * K;

    float acc[4][4][4];
    #pragma unroll
    for (int i = 0; i < 4; i++)
        #pragma unroll
        for (int j = 0; j < 4; j++)
            #pragma unroll
            for (int q = 0; q < 4; q++) acc[i][j][q] = 0.f;

    mma_mainloop<4>(Ab, lda, Bb, K, K, acc, dyn);

    const int wid = threadIdx.x >> 5, lane = threadIdx.x & 31;
    const int wm = wid >> 2, wn = wid & 3;
    const int gid = lane >> 2, tig = lane & 3;
    const int mW = mBase + wm * 64;
    const int nW = nBase + wn * 32;

    #pragma unroll
    for (int mi = 0; mi < 4; mi++) {
        #pragma unroll
        for (int half_ = 0; half_ < 2; half_++) {
            const int row = mW + mi * 16 + gid + half_ * 8;
            #pragma unroll
            for (int ni = 0; ni < 4; ni++) {
                const int col = nW + ni * 8 + tig * 2;
                float v0 = acc[mi][ni][half_ * 2 + 0] + bias[col];
                float v1 = acc[mi][ni][half_ * 2 + 1] + bias[col + 1];
                if (RELU) { v0 = fmaxf(v0, 0.f); v1 = fmaxf(v1, 0.f); }
                if (OUT_HALF) {
                    __half* cRow = (__half*)Cv + (size_t)row * ldc;
                    *reinterpret_cast<__half2*>(cRow + col) = __floats2half2_rn(v0, v1);
                } else {
                    float* cRow = (float*)Cv + (size_t)row * ldc;
                    if (res) {
                        const float* rRow = res + (size_t)row * ldc;
                        v0 += rRow[col]; v1 += rRow[col + 1];
                    }
                    *reinterpret_cast<float2*>(cRow + col) = make_float2(v0, v1);
                }
            }
        }
    }
}

// ---------------- fused flash attention ---------------------------------
// grid (8 m-tiles, 64 bh); 256 threads = 8 warps; warp owns 16 rows x all 128 kv cols.
__global__ __launch_bounds__(256) void flash_kernel(
    const __half* __restrict__ qkv, const __half* __restrict__ vt,
    const int* __restrict__ mask, __half* __restrict__ ctx)
{
    extern __shared__ char dyn[];
    const uint32_t sb = smem_u32(dyn);
    float* sMask = (float*)(dyn + 2 * (QSZ + 2 * KSZ + 2 * VSZ));

    const int bh = blockIdx.y, b = bh >> 4, h = bh & 15;
    const int mBase = blockIdx.x * 128;
    const int tid = threadIdx.x, wid = tid >> 5, lane = tid & 31;
    const int gid = lane >> 2, tig = lane & 3;

    #pragma unroll
    for (int it = 0; it < 4; it++) {
        const int i = tid + it * 256;
        sMask[i] = (mask[b * SSZ + i] == 0) ? -60000.f : 0.f;
    }

    {
        const __half* Qg = qkv + (size_t)(b * SSZ + mBase) * QKVLD + h * 64;
        #pragma unroll
        for (int it = 0; it < 4; it++) {
            const int idx = tid + it * 256;
            const int r = idx >> 3, c = idx & 7;
            cpasync16(sb + (uint32_t)(r * LDQ + c * 8) * 2,
                      Qg + (size_t)r * QKVLD + c * 8);
        }
    }
    const __half* Kg0 = qkv + (size_t)(b * SSZ) * QKVLD + 1024 + h * 64;
    const __half* Vg0 = vt + (size_t)bh * 64 * SSZ;
    auto load_kv = [&](int stage, int t) {
        const __half* Kg = Kg0 + (size_t)(t * 128) * QKVLD;
        const uint32_t kS = sb + (uint32_t)((QSZ + stage * KSZ) * 2);
        #pragma unroll
        for (int it = 0; it < 4; it++) {
            const int idx = tid + it * 256;
            const int r = idx >> 3, c = idx & 7;
            cpasync16(kS + (uint32_t)(r * LDK + c * 8) * 2,
                      Kg + (size_t)r * QKVLD + c * 8);
        }
        const __half* Vg = Vg0 + t * 128;
        const uint32_t vS = sb + (uint32_t)((QSZ + 2 * KSZ + stage * VSZ) * 2);
        #pragma unroll
        for (int it = 0; it < 4; it++) {
            const int idx = tid + it * 256;
            const int r = idx >> 4, c = idx & 15;
            cpasync16(vS + (uint32_t)(r * LDV + c * 8) * 2,
                      Vg + (size_t)r * SSZ + c * 8);
        }
    };
    load_kv(0, 0);
    CP_COMMIT();

    const uint32_t aOffQ = (uint32_t)(((wid * 16 + (lane & 15)) * LDQ + ((lane >> 4) << 3)) * 2);
    const uint32_t bOffK = (uint32_t)((((lane & 7) + ((lane >> 4) << 3)) * LDK + (((lane >> 3) & 1) << 3)) * 2);
    const uint32_t bOffV = (uint32_t)((((lane & 7) + ((lane >> 4) << 3)) * LDV + (((lane >> 3) & 1) << 3)) * 2);

    uint32_t qf[4][4];
    float oacc[8][4];
    #pragma unroll
    for (int i = 0; i < 8; i++)
        #pragma unroll
        for (int q = 0; q < 4; q++) oacc[i][q] = 0.f;
    float m0 = -1e30f, m1 = -1e30f, l0 = 0.f, l1 = 0.f;

    for (int t = 0; t < 8; t++) {
        __syncthreads();
        if (t < 7) { load_kv((t + 1) & 1, t + 1); CP_COMMIT(); CP_WAIT1(); }
        else       { CP_WAIT0(); }
        __syncthreads();

        if (t == 0) {
            #pragma unroll
            for (int ks = 0; ks < 4; ks++)
                ldsm4(sb + aOffQ + ks * 32,
                      qf[ks][0], qf[ks][1], qf[ks][2], qf[ks][3]);
        }

        float sacc[16][4];
        #pragma unroll
        for (int ni = 0; ni < 16; ni++)
            #pragma unroll
            for (int q = 0; q < 4; q++) sacc[ni][q] = 0.f;

        const uint32_t kb = sb + (uint32_t)((QSZ + (t & 1) * KSZ) * 2) + bOffK;
        #pragma unroll
        for (int ks = 0; ks < 4; ks++) {
            uint32_t bfr[16][2];
            #pragma unroll
            for (int np = 0; np < 8; np++)
                ldsm4(kb + ks * 32 + (uint32_t)(np * 16 * LDK) * 2,
                      bfr[2 * np][0], bfr[2 * np][1],
                      bfr[2 * np + 1][0], bfr[2 * np + 1][1]);
            #pragma unroll
            for (int ni = 0; ni < 16; ni++)
                mma_f16(sacc[ni], qf[ks], bfr[ni]);
        }

        float tm0 = -1e30f, tm1 = -1e30f;
        #pragma unroll
        for (int ni = 0; ni < 16; ni++) {
            const int colb = t * 128 + ni * 8 + 2 * tig;
            const float ma = sMask[colb], mb = sMask[colb + 1];
            sacc[ni][0] = sacc[ni][0] * 0.125f + ma;
            sacc[ni][1] = sacc[ni][1] * 0.125f + mb;
            sacc[ni][2] = sacc[ni][2] * 0.125f + ma;
            sacc[ni][3] = sacc[ni][3] * 0.125f + mb;
            tm0 = fmaxf(tm0, fmaxf(sacc[ni][0], sacc[ni][1]));
            tm1 = fmaxf(tm1, fmaxf(sacc[ni][2], sacc[ni][3]));
        }
        tm0 = fmaxf(tm0, __shfl_xor_sync(0xffffffffu, tm0, 1));
        tm0 = fmaxf(tm0, __shfl_xor_sync(0xffffffffu, tm0, 2));
        tm1 = fmaxf(tm1, __shfl_xor_sync(0xffffffffu, tm1, 1));
        tm1 = fmaxf(tm1, __shfl_xor_sync(0xffffffffu, tm1, 2));

        const float mn0 = fmaxf(m0, tm0), mn1 = fmaxf(m1, tm1);
        const float c0 = __expf(m0 - mn0), c1 = __expf(m1 - mn1);
        m0 = mn0; m1 = mn1;

        float ls0 = 0.f, ls1 = 0.f;
        #pragma unroll
        for (int ni = 0; ni < 16; ni++) {
            sacc[ni][0] = __expf(sacc[ni][0] - m0);
            sacc[ni][1] = __expf(sacc[ni][1] - m0);
            sacc[ni][2] = __expf(sacc[ni][2] - m1);
            sacc[ni][3] = __expf(sacc[ni][3] - m1);
            ls0 += sacc[ni][0] + sacc[ni][1];
            ls1 += sacc[ni][2] + sacc[ni][3];
        }
        l0 = l0 * c0 + ls0;
        l1 = l1 * c1 + ls1;
        #pragma unroll
        for (int ni = 0; ni < 8; ni++) {
            oacc[ni][0] *= c0; oacc[ni][1] *= c0;
            oacc[ni][2] *= c1; oacc[ni][3] *= c1;
        }

        const uint32_t vb = sb + (uint32_t)((QSZ + 2 * KSZ + (t & 1) * VSZ) * 2) + bOffV;
        #pragma unroll
        for (int j = 0; j < 8; j++) {
            uint32_t pf[4];
            {
                __half2 p0 = __floats2half2_rn(sacc[2 * j][0],     sacc[2 * j][1]);
                __half2 p1 = __floats2half2_rn(sacc[2 * j][2],     sacc[2 * j][3]);
                __half2 p2 = __floats2half2_rn(sacc[2 * j + 1][0], sacc[2 * j + 1][1]);
                __half2 p3 = __floats2half2_rn(sacc[2 * j + 1][2], sacc[2 * j + 1][3]);
                pf[0] = *reinterpret_cast<uint32_t*>(&p0);
                pf[1] = *reinterpret_cast<uint32_t*>(&p1);
                pf[2] = *reinterpret_cast<uint32_t*>(&p2);
                pf[3] = *reinterpret_cast<uint32_t*>(&p3);
            }
            uint32_t bfr2[8][2];
            #pragma unroll
            for (int np = 0; np < 4; np++)
                ldsm4(vb + j * 32 + (uint32_t)(np * 16 * LDV) * 2,
                      bfr2[2 * np][0], bfr2[2 * np][1],
                      bfr2[2 * np + 1][0], bfr2[2 * np + 1][1]);
            #pragma unroll
            for (int ni = 0; ni < 8; ni++)
                mma_f16(oacc[ni], pf, bfr2[ni]);
        }
    }

    l0 += __shfl_xor_sync(0xffffffffu, l0, 1);
    l0 += __shfl_xor_sync(0xffffffffu, l0, 2);
    l1 += __shfl_xor_sync(0xffffffffu, l1, 1);
    l1 += __shfl_xor_sync(0xffffffffu, l1, 2);
    const float inv0 = 1.f / l0, inv1 = 1.f / l1;

    const int row0 = mBase + wid * 16 + gid;
    __half* o0 = ctx + (size_t)(b * SSZ + row0) * DDM + h * 64;
    __half* o1 = o0 + 8 * DDM;
    #pragma unroll
    for (int ni = 0; ni < 8; ni++) {
        const int col = ni * 8 + 2 * tig;
        *reinterpret_cast<__half2*>(o0 + col) =
            __floats2half2_rn(oacc[ni][0] * inv0, oacc[ni][1] * inv0);
        *reinterpret_cast<__half2*>(o1 + col) =
            __floats2half2_rn(oacc[ni][2] * inv1, oacc[ni][3] * inv1);
    }
}

// ---------------- LayerNorm (ddof=1, eps on std, scalar a/b), half out --
__global__ __launch_bounds__(256) void ln_kernel(const float* __restrict__ x,
                                                 __half* __restrict__ y,
                                                 const float* __restrict__ alpha,
                                                 const float* __restrict__ beta)
{
    __shared__ float red[256];
    const int row = blockIdx.x, tid = threadIdx.x;
    const float* xr = x + (size_t)row * DDM;
    __half* yr = y + (size_t)row * DDM;

    float4 v = reinterpret_cast<const float4*>(xr)[tid];
    red[tid] = v.x + v.y + v.z + v.w; __syncthreads();
    for (int o = 128; o > 0; o >>= 1) { if (tid < o) red[tid] += red[tid + o]; __syncthreads(); }
    const float mean = red[0] * (1.0f / DDM);
    __syncthreads();

    float4 d = make_float4(v.x - mean, v.y - mean, v.z - mean, v.w - mean);
    red[tid] = d.x * d.x + d.y * d.y + d.z * d.z + d.w * d.w; __syncthreads();
    for (int o = 128; o > 0; o >>= 1) { if (tid < o) red[tid] += red[tid + o]; __syncthreads(); }
    const float stdv = sqrtf(red[0] * (1.0f / (DDM - 1)));
    const float a = alpha[0], bta = beta[0];
    const float inv = a / (stdv + 1e-6f);

    __half2 o0 = __floats2half2_rn(d.x * inv + bta, d.y * inv + bta);
    __half2 o1 = __floats2half2_rn(d.z * inv + bta, d.w * inv + bta);
    uint2 pk;
    pk.x = *reinterpret_cast<uint32_t*>(&o0);
    pk.y = *reinterpret_cast<uint32_t*>(&o1);
    reinterpret_cast<uint2*>(yr)[tid] = pk;
}

// ---------------- merged weight transpose (all 6 matrices, 1 launch) -----
__global__ void wtrans_all_kernel(const float* __restrict__ wq, const float* __restrict__ wk,
                                  const float* __restrict__ wv, const float* __restrict__ wo,
                                  const float* __restrict__ w1, const float* __restrict__ w2,
                                  __half* __restrict__ wqkvt, __half* __restrict__ wot,
                                  __half* __restrict__ w1t,   __half* __restrict__ w2t)
{
    __shared__ float t[32][33];
    int tIdx = blockIdx.x;
    const float* src; __half* dst; int R, C;
    if (tIdx < 3072) {
        const int m = tIdx >> 10;
        src = (m == 0) ? wq : (m == 1) ? wk : wv;
        dst = wqkvt + (size_t)m * 1024 * 1024;
        R = 1024; C = 1024; tIdx &= 1023;
    } else if (tIdx < 4096) {
        src = wo; dst = wot; R = 1024; C = 1024; tIdx -= 3072;
    } else if (tIdx < 8192) {
        src = w1; dst = w1t; R = 1024; C = 4096; tIdx -= 4096;
    } else {
        src = w2; dst = w2t; R = 4096; C = 1024; tIdx -= 8192;
    }
    const int nCx = C >> 5;
    const int c0 = (tIdx % nCx) * 32, r0 = (tIdx / nCx) * 32;
    const int tx = threadIdx.x, ty = threadIdx.y;
    #pragma unroll
    for (int i = ty; i < 32; i += 8)
        t[i][tx] = src[(size_t)(r0 + i) * C + c0 + tx];
    __syncthreads();
    #pragma unroll
    for (int i = ty; i < 32; i += 8)
        dst[(size_t)(c0 + i) * R + r0 + tx] = __float2half_rn(t[tx][i]);
}

__global__ void vtrans_kernel(const __half* __restrict__ qkv, __half* __restrict__ vt)
{
    __shared__ __half t[32][34];
    const int bh = blockIdx.z, b = bh >> 4, h = bh & 15;
    const int s0 = blockIdx.x * 32, d0 = blockIdx.y * 32;
    const int tx = threadIdx.x, ty = threadIdx.y;
    #pragma unroll
    for (int i = ty; i < 32; i += 8)
        t[i][tx] = qkv[(size_t)(b * SSZ + s0 + i) * QKVLD + 2048 + h * 64 + d0 + tx];
    __syncthreads();
    #pragma unroll
    for (int i = ty; i < 32; i += 8)
        vt[(size_t)bh * 64 * SSZ + (size_t)(d0 + i) * SSZ + s0 + tx] = t[tx][i];
}

__global__ void bcat_kernel(const float* __restrict__ bq, const float* __restrict__ bk,
                            const float* __restrict__ bv, float* __restrict__ dst)
{
    const int i = blockIdx.x * 256 + threadIdx.x;
    if (i < 1024) dst[i] = bq[i];
    else if (i < 2048) dst[i] = bk[i - 1024];
    else dst[i] = bv[i - 2048];
}

// ---------------- launch ----------------
extern "C" void kernel_launch(void* const* d_in, const int* in_sizes, int n_in,
                              void* d_out, int out_size)
{
    const float* x      = (const float*)d_in[0];
    const int*   mask   = (const int*)  d_in[1];
    const float* wq     = (const float*)d_in[2];
    const float* bq     = (const float*)d_in[3];
    const float* wk     = (const float*)d_in[4];
    const float* bk     = (const float*)d_in[5];
    const float* wv     = (const float*)d_in[6];
    const float* bv     = (const float*)d_in[7];
    const float* wo     = (const float*)d_in[8];
    const float* bo     = (const float*)d_in[9];
    const float* w1     = (const float*)d_in[10];
    const float* b1     = (const float*)d_in[11];
    const float* w2     = (const float*)d_in[12];
    const float* b2     = (const float*)d_in[13];
    const float* alpha1 = (const float*)d_in[14];
    const float* beta1  = (const float*)d_in[15];
    const float* alpha2 = (const float*)d_in[16];
    const float* beta2  = (const float*)d_in[17];
    float* out = (float*)d_out;

    const int SMEM128 = 3 * (128 * SA2 * 2 + 128 * SA2 * 2);   // 61440
    cudaFuncSetAttribute((const void*)gemm_mma_kernel<1, 0>, cudaFuncAttributeMaxDynamicSharedMemorySize, SMEM128);
    cudaFuncSetAttribute((const void*)gemm_mma_kernel<1, 1>, cudaFuncAttributeMaxDynamicSharedMemorySize, SMEM128);
    cudaFuncSetAttribute((const void*)gemm_mma_kernel<0, 0>, cudaFuncAttributeMaxDynamicSharedMemorySize, SMEM128);
    cudaFuncSetAttribute((const void*)flash_kernel,          cudaFuncAttributeMaxDynamicSharedMemorySize, FL_SMEM);

    __half *xn, *qkv, *vt, *ctx, *ff, *wqkvt, *wot, *w1t, *w2t;
    float *x1, *bqkv;
    cudaGetSymbolAddress((void**)&xn,    g_xn);
    cudaGetSymbolAddress((void**)&qkv,   g_qkv);
    cudaGetSymbolAddress((void**)&vt,    g_vt);
    cudaGetSymbolAddress((void**)&ctx,   g_ctx);
    cudaGetSymbolAddress((void**)&x1,    g_x1);
    cudaGetSymbolAddress((void**)&ff,    g_ff);
    cudaGetSymbolAddress((void**)&wqkvt, g_wqkvt);
    cudaGetSymbolAddress((void**)&wot,   g_wot);
    cudaGetSymbolAddress((void**)&w1t,   g_w1t);
    cudaGetSymbolAddress((void**)&w2t,   g_w2t);
    cudaGetSymbolAddress((void**)&bqkv,  g_bqkv);

    dim3 tb(32, 8);
    // 0: all weight transposes fp32 -> fp16 K-major
    wtrans_all_kernel<<<12288, tb>>>(wq, wk, wv, wo, w1, w2, wqkvt, wot, w1t, w2t);
    // 1: bias concat
    bcat_kernel<<<12, 256>>>(bq, bk, bv, bqkv);
    // 2: LN1
    ln_kernel<<<ROWS, 256>>>(x, xn, alpha1, beta1);
    // 3: fused QKV projection (half out)
    gemm_mma_kernel<1, 0><<<dim3(24, 32), 256, SMEM128>>>(xn, DDM, wqkvt, bqkv,
                                                          nullptr, qkv, QKVLD, DDM);
    // 4: V transpose to [bh][d][s]
    vtrans_kernel<<<dim3(32, 2, BHH), tb>>>(qkv, vt);
    // 5: fused flash attention
    flash_kernel<<<dim3(8, BHH), 256, FL_SMEM>>>(qkv, vt, mask, ctx);
    // 6: output projection + residual (float out)
    gemm_mma_kernel<0, 0><<<dim3(8, 32), 256, SMEM128>>>(ctx, DDM, wot, bo,
                                                         x, x1, DDM, DDM);
    // 7: LN2
    ln_kernel<<<ROWS, 256>>>(x1, xn, alpha2, beta2);
    // 8: FF1 (relu, half out)
    gemm_mma_kernel<1, 1><<<dim3(32, 32), 256, SMEM128>>>(xn, DDM, w1t, b1,
                                                          nullptr, ff, DFF, DDM);
    // 9: FF2 + residual (float out)
    gemm_mma_kernel<0, 0><<<dim3(8, 32), 256, SMEM128>>>(ff, DFF, w2t, b2,
                                                         x1, out, DDM, DFF);
}

// round 8
// speedup vs baseline: 8.2680x; 1.0149x over previous
#include <cuda_runtime.h>
#include <cuda_fp16.h>
#include <cstdint>

// ---------------- problem dims ----------------
#define BBX   4
#define SSZ   1024
#define DDM   1024
#define HHX   16
#define DFF   4096
#define ROWS  4096          // BBX*SSZ
#define BHH   64            // BBX*HHX
#define QKVLD 3072
#define SAW   72            // GEMM smem stride (halfs) for BK=64

// flash-attention smem strides (halfs)
#define LDQ   72
#define LDK   72
#define LDV   136
#define QSZ   (128 * LDQ)       // 9216 halfs
#define KSZ   (128 * LDK)       // 9216 halfs
#define VSZ   (64 * LDV)        // 8704 halfs
#define FL_SMEM (2 * (QSZ + 2 * KSZ + 2 * VSZ) + 4096)   // 94208 bytes

// GEMM smem
#define G_ASZ (128 * SAW * 2)        // 18432 B
#define G_STG (2 * G_ASZ)            // 36864 B
#define G_SMEM (3 * G_STG)           // 110592 B

// ---------------- scratch (static device globals) ----------------
__device__ __half g_xn   [(size_t)ROWS * DDM];
__device__ __half g_qkv  [(size_t)ROWS * QKVLD];
__device__ __half g_vt   [(size_t)BHH * 64 * SSZ];
__device__ __half g_ctx  [(size_t)ROWS * DDM];
__device__ float  g_x1   [(size_t)ROWS * DDM];
__device__ __half g_ff   [(size_t)ROWS * DFF];
__device__ __half g_wqkvt[(size_t)QKVLD * DDM];
__device__ __half g_wot  [(size_t)DDM * DDM];
__device__ __half g_w1t  [(size_t)DFF * DDM];
__device__ __half g_w2t  [(size_t)DDM * DFF];
__device__ float  g_bqkv [QKVLD];

// ---------------- helpers ----------------
__device__ __forceinline__ uint32_t smem_u32(const void* p) {
    uint32_t a;
    asm("{ .reg .u64 t; cvta.to.shared.u64 t, %1; cvt.u32.u64 %0, t; }"
        : "=r"(a) : "l"(p));
    return a;
}
__device__ __forceinline__ void cpasync16(uint32_t s, const void* g) {
    asm volatile("cp.async.cg.shared.global [%0], [%1], 16;" :: "r"(s), "l"(g));
}
#define CP_COMMIT() asm volatile("cp.async.commit_group;" ::: "memory")
#define CP_WAIT1()  asm volatile("cp.async.wait_group 1;" ::: "memory")
#define CP_WAIT0()  asm volatile("cp.async.wait_group 0;" ::: "memory")

__device__ __forceinline__ void ldsm4(uint32_t addr, uint32_t& r0, uint32_t& r1,
                                      uint32_t& r2, uint32_t& r3) {
    asm volatile("ldmatrix.sync.aligned.m8n8.x4.shared.b16 {%0,%1,%2,%3}, [%4];"
                 : "=r"(r0), "=r"(r1), "=r"(r2), "=r"(r3) : "r"(addr));
}

__device__ __forceinline__ void mma_f16(float (&d)[4],
                                        const uint32_t (&a)[4],
                                        const uint32_t (&b)[2]) {
    asm volatile(
        "mma.sync.aligned.m16n8k16.row.col.f32.f16.f16.f32 "
        "{%0,%1,%2,%3},{%4,%5,%6,%7},{%8,%9},{%0,%1,%2,%3};"
        : "+f"(d[0]), "+f"(d[1]), "+f"(d[2]), "+f"(d[3])
        : "r"(a[0]), "r"(a[1]), "r"(a[2]), "r"(a[3]),
          "r"(b[0]), "r"(b[1]));
}

// ---------------- GEMM: cp.async tile loader (one BK=64 chunk, halfs) ----
__device__ __forceinline__ void load_chunk64(const __half* __restrict__ A, int lda,
                                             const __half* __restrict__ B, int ldb,
                                             int k0, uint32_t sA, uint32_t sB, int tid)
{
    #pragma unroll
    for (int it = 0; it < 4; it++) {            // A: 128 rows x 8 xfers of 8 halfs
        const int idx = tid + it * 256;
        const int r = idx >> 3, c = idx & 7;
        cpasync16(sA + (uint32_t)(r * SAW + c * 8) * 2,
                  A + (size_t)r * lda + k0 + c * 8);
    }
    #pragma unroll
    for (int it = 0; it < 4; it++) {            // B: 128 rows
        const int idx = tid + it * 256;
        const int r = idx >> 3, c = idx & 7;
        cpasync16(sB + (uint32_t)(r * SAW + c * 8) * 2,
                  B + (size_t)r * ldb + k0 + c * 8);
    }
}

// fragment loads for one k16 step (A 64 rows, B 32 rows per warp)
__device__ __forceinline__ void ld_frags(uint32_t aB, uint32_t bB,
                                         uint32_t (&af)[4][4], uint32_t (&bf)[4][2])
{
    #pragma unroll
    for (int mi = 0; mi < 4; mi++)
        ldsm4(aB + (uint32_t)(mi * 16 * SAW) * 2,
              af[mi][0], af[mi][1], af[mi][2], af[mi][3]);
    #pragma unroll
    for (int np = 0; np < 2; np++)
        ldsm4(bB + (uint32_t)(np * 16 * SAW) * 2,
              bf[2 * np][0], bf[2 * np][1],
              bf[2 * np + 1][0], bf[2 * np + 1][1]);
}

#define MMA_BATCH(af, bf)                               \
    _Pragma("unroll")                                   \
    for (int mi = 0; mi < 4; mi++)                      \
        _Pragma("unroll")                               \
        for (int ni = 0; ni < 4; ni++)                  \
            mma_f16(acc[mi][ni], (af)[mi], (bf)[ni]);

// ---------------- GEMM mainloop: BK=64, 3 stages, frag double buffer ----
__device__ __forceinline__ void mma_mainloop(const __half* __restrict__ A, int lda,
                                             const __half* __restrict__ B, int ldb,
                                             int K, float (&acc)[4][4][4], char* dyn)
{
    const int tid = threadIdx.x;
    const int wid = tid >> 5, lane = tid & 31;
    const int wm = wid >> 2, wn = wid & 3;
    const uint32_t sbase = smem_u32(dyn);

    const uint32_t aOff = (uint32_t)(((wm * 64 + (lane & 15)) * SAW + ((lane >> 4) << 3)) * 2);
    const uint32_t bOff = (uint32_t)(((wn * 32 + (lane & 7) + ((lane >> 4) << 3)) * SAW
                                      + (((lane >> 3) & 1) << 3)) * 2);

    const int nk = K >> 6;                      // K is 1024 or 4096 -> nk >= 16
    load_chunk64(A, lda, B, ldb, 0, sbase, sbase + G_ASZ, tid);
    CP_COMMIT();
    load_chunk64(A, lda, B, ldb, 64, sbase + G_STG, sbase + G_STG + G_ASZ, tid);
    CP_COMMIT();
    CP_WAIT1();
    __syncthreads();

    uint32_t af0[4][4], bf0[4][2], af1[4][4], bf1[4][2];
    ld_frags(sbase + aOff, sbase + G_ASZ + bOff, af0, bf0);

    for (int c = 0; c < nk; c++) {
        const int s = c % 3;
        if (c + 2 < nk) {
            const int s2 = (c + 2) % 3;
            load_chunk64(A, lda, B, ldb, (c + 2) * 64,
                         sbase + s2 * G_STG, sbase + s2 * G_STG + G_ASZ, tid);
        }
        CP_COMMIT();

        const uint32_t aB = sbase + s * G_STG + aOff;
        const uint32_t bB = sbase + s * G_STG + G_ASZ + bOff;

        ld_frags(aB + 32, bB + 32, af1, bf1);       // ks1
        MMA_BATCH(af0, bf0);                        // ks0
        ld_frags(aB + 64, bB + 64, af0, bf0);       // ks2
        MMA_BATCH(af1, bf1);                        // ks1
        ld_frags(aB + 96, bB + 96, af1, bf1);       // ks3
        MMA_BATCH(af0, bf0);                        // ks2

        if (c + 1 < nk) {
            CP_WAIT1();
            __syncthreads();
            const int s1 = (c + 1) % 3;
            ld_frags(sbase + s1 * G_STG + aOff,
                     sbase + s1 * G_STG + G_ASZ + bOff, af0, bf0);  // next ks0
        }
        MMA_BATCH(af1, bf1);                        // ks3
    }
}

// ---------------- dense GEMM: C = A.Bt^T + bias (+relu) (+res) ---------
template <int OUT_HALF, int RELU>
__global__ __launch_bounds__(256, 2) void gemm_mma_kernel(
    const __half* __restrict__ A, int lda,
    const __half* __restrict__ Bt,
    const float* __restrict__ bias, const float* __restrict__ res,
    void* __restrict__ Cv, int ldc, int K)
{
    extern __shared__ char dyn[];
    const int mBase = blockIdx.y * 128;
    const int nBase = blockIdx.x * 128;
    const __half* Ab = A + (size_t)mBase * lda;
    const __half* Bb = Bt + (size_t)nBase * K;

    float acc[4][4][4];
    #pragma unroll
    for (int i = 0; i < 4; i++)
        #pragma unroll
        for (int j = 0; j < 4; j++)
            #pragma unroll
            for (int q = 0; q < 4; q++) acc[i][j][q] = 0.f;

    mma_mainloop(Ab, lda, Bb, K, K, acc, dyn);

    const int wid = threadIdx.x >> 5, lane = threadIdx.x & 31;
    const int wm = wid >> 2, wn = wid & 3;
    const int gid = lane >> 2, tig = lane & 3;
    const int mW = mBase + wm * 64;
    const int nW = nBase + wn * 32;

    #pragma unroll
    for (int mi = 0; mi < 4; mi++) {
        #pragma unroll
        for (int half_ = 0; half_ < 2; half_++) {
            const int row = mW + mi * 16 + gid + half_ * 8;
            #pragma unroll
            for (int ni = 0; ni < 4; ni++) {
                const int col = nW + ni * 8 + tig * 2;
                float v0 = acc[mi][ni][half_ * 2 + 0] + bias[col];
                float v1 = acc[mi][ni][half_ * 2 + 1] + bias[col + 1];
                if (RELU) { v0 = fmaxf(v0, 0.f); v1 = fmaxf(v1, 0.f); }
                if (OUT_HALF) {
                    __half* cRow = (__half*)Cv + (size_t)row * ldc;
                    *reinterpret_cast<__half2*>(cRow + col) = __floats2half2_rn(v0, v1);
                } else {
                    float* cRow = (float*)Cv + (size_t)row * ldc;
                    if (res) {
                        const float* rRow = res + (size_t)row * ldc;
                        v0 += rRow[col]; v1 += rRow[col + 1];
                    }
                    *reinterpret_cast<float2*>(cRow + col) = make_float2(v0, v1);
                }
            }
        }
    }
}

// ---------------- fused flash attention ---------------------------------
// grid (8 m-tiles, 64 bh); 256 threads = 8 warps; warp owns 16 rows x all 128 kv cols.
__global__ __launch_bounds__(256) void flash_kernel(
    const __half* __restrict__ qkv, const __half* __restrict__ vt,
    const int* __restrict__ mask, __half* __restrict__ ctx)
{
    extern __shared__ char dyn[];
    const uint32_t sb = smem_u32(dyn);
    float* sMask = (float*)(dyn + 2 * (QSZ + 2 * KSZ + 2 * VSZ));

    const int bh = blockIdx.y, b = bh >> 4, h = bh & 15;
    const int mBase = blockIdx.x * 128;
    const int tid = threadIdx.x, wid = tid >> 5, lane = tid & 31;
    const int gid = lane >> 2, tig = lane & 3;

    #pragma unroll
    for (int it = 0; it < 4; it++) {
        const int i = tid + it * 256;
        sMask[i] = (mask[b * SSZ + i] == 0) ? -60000.f : 0.f;
    }

    {
        const __half* Qg = qkv + (size_t)(b * SSZ + mBase) * QKVLD + h * 64;
        #pragma unroll
        for (int it = 0; it < 4; it++) {
            const int idx = tid + it * 256;
            const int r = idx >> 3, c = idx & 7;
            cpasync16(sb + (uint32_t)(r * LDQ + c * 8) * 2,
                      Qg + (size_t)r * QKVLD + c * 8);
        }
    }
    const __half* Kg0 = qkv + (size_t)(b * SSZ) * QKVLD + 1024 + h * 64;
    const __half* Vg0 = vt + (size_t)bh * 64 * SSZ;
    auto load_kv = [&](int stage, int t) {
        const __half* Kg = Kg0 + (size_t)(t * 128) * QKVLD;
        const uint32_t kS = sb + (uint32_t)((QSZ + stage * KSZ) * 2);
        #pragma unroll
        for (int it = 0; it < 4; it++) {
            const int idx = tid + it * 256;
            const int r = idx >> 3, c = idx & 7;
            cpasync16(kS + (uint32_t)(r * LDK + c * 8) * 2,
                      Kg + (size_t)r * QKVLD + c * 8);
        }
        const __half* Vg = Vg0 + t * 128;
        const uint32_t vS = sb + (uint32_t)((QSZ + 2 * KSZ + stage * VSZ) * 2);
        #pragma unroll
        for (int it = 0; it < 4; it++) {
            const int idx = tid + it * 256;
            const int r = idx >> 4, c = idx & 15;
            cpasync16(vS + (uint32_t)(r * LDV + c * 8) * 2,
                      Vg + (size_t)r * SSZ + c * 8);
        }
    };
    load_kv(0, 0);
    CP_COMMIT();

    const uint32_t aOffQ = (uint32_t)(((wid * 16 + (lane & 15)) * LDQ + ((lane >> 4) << 3)) * 2);
    const uint32_t bOffK = (uint32_t)((((lane & 7) + ((lane >> 4) << 3)) * LDK + (((lane >> 3) & 1) << 3)) * 2);
    const uint32_t bOffV = (uint32_t)((((lane & 7) + ((lane >> 4) << 3)) * LDV + (((lane >> 3) & 1) << 3)) * 2);

    uint32_t qf[4][4];
    float oacc[8][4];
    #pragma unroll
    for (int i = 0; i < 8; i++)
        #pragma unroll
        for (int q = 0; q < 4; q++) oacc[i][q] = 0.f;
    float m0 = -1e30f, m1 = -1e30f, l0 = 0.f, l1 = 0.f;

    for (int t = 0; t < 8; t++) {
        __syncthreads();
        if (t < 7) { load_kv((t + 1) & 1, t + 1); CP_COMMIT(); CP_WAIT1(); }
        else       { CP_WAIT0(); }
        __syncthreads();

        if (t == 0) {
            #pragma unroll
            for (int ks = 0; ks < 4; ks++)
                ldsm4(sb + aOffQ + ks * 32,
                      qf[ks][0], qf[ks][1], qf[ks][2], qf[ks][3]);
        }

        float sacc[16][4];
        #pragma unroll
        for (int ni = 0; ni < 16; ni++)
            #pragma unroll
            for (int q = 0; q < 4; q++) sacc[ni][q] = 0.f;

        const uint32_t kb = sb + (uint32_t)((QSZ + (t & 1) * KSZ) * 2) + bOffK;
        #pragma unroll
        for (int ks = 0; ks < 4; ks++) {
            uint32_t bfr[16][2];
            #pragma unroll
            for (int np = 0; np < 8; np++)
                ldsm4(kb + ks * 32 + (uint32_t)(np * 16 * LDK) * 2,
                      bfr[2 * np][0], bfr[2 * np][1],
                      bfr[2 * np + 1][0], bfr[2 * np + 1][1]);
            #pragma unroll
            for (int ni = 0; ni < 16; ni++)
                mma_f16(sacc[ni], qf[ks], bfr[ni]);
        }

        float tm0 = -1e30f, tm1 = -1e30f;
        #pragma unroll
        for (int ni = 0; ni < 16; ni++) {
            const int colb = t * 128 + ni * 8 + 2 * tig;
            const float ma = sMask[colb], mb = sMask[colb + 1];
            sacc[ni][0] = sacc[ni][0] * 0.125f + ma;
            sacc[ni][1] = sacc[ni][1] * 0.125f + mb;
            sacc[ni][2] = sacc[ni][2] * 0.125f + ma;
            sacc[ni][3] = sacc[ni][3] * 0.125f + mb;
            tm0 = fmaxf(tm0, fmaxf(sacc[ni][0], sacc[ni][1]));
            tm1 = fmaxf(tm1, fmaxf(sacc[ni][2], sacc[ni][3]));
        }
        tm0 = fmaxf(tm0, __shfl_xor_sync(0xffffffffu, tm0, 1));
        tm0 = fmaxf(tm0, __shfl_xor_sync(0xffffffffu, tm0, 2));
        tm1 = fmaxf(tm1, __shfl_xor_sync(0xffffffffu, tm1, 1));
        tm1 = fmaxf(tm1, __shfl_xor_sync(0xffffffffu, tm1, 2));

        const float mn0 = fmaxf(m0, tm0), mn1 = fmaxf(m1, tm1);
        const float c0 = __expf(m0 - mn0), c1 = __expf(m1 - mn1);
        m0 = mn0; m1 = mn1;

        float ls0 = 0.f, ls1 = 0.f;
        #pragma unroll
        for (int ni = 0; ni < 16; ni++) {
            sacc[ni][0] = __expf(sacc[ni][0] - m0);
            sacc[ni][1] = __expf(sacc[ni][1] - m0);
            sacc[ni][2] = __expf(sacc[ni][2] - m1);
            sacc[ni][3] = __expf(sacc[ni][3] - m1);
            ls0 += sacc[ni][0] + sacc[ni][1];
            ls1 += sacc[ni][2] + sacc[ni][3];
        }
        l0 = l0 * c0 + ls0;
        l1 = l1 * c1 + ls1;
        #pragma unroll
        for (int ni = 0; ni < 8; ni++) {
            oacc[ni][0] *= c0; oacc[ni][1] *= c0;
            oacc[ni][2] *= c1; oacc[ni][3] *= c1;
        }

        const uint32_t vb = sb + (uint32_t)((QSZ + 2 * KSZ + (t & 1) * VSZ) * 2) + bOffV;
        #pragma unroll
        for (int j = 0; j < 8; j++) {
            uint32_t pf[4];
            {
                __half2 p0 = __floats2half2_rn(sacc[2 * j][0],     sacc[2 * j][1]);
                __half2 p1 = __floats2half2_rn(sacc[2 * j][2],     sacc[2 * j][3]);
                __half2 p2 = __floats2half2_rn(sacc[2 * j + 1][0], sacc[2 * j + 1][1]);
                __half2 p3 = __floats2half2_rn(sacc[2 * j + 1][2], sacc[2 * j + 1][3]);
                pf[0] = *reinterpret_cast<uint32_t*>(&p0);
                pf[1] = *reinterpret_cast<uint32_t*>(&p1);
                pf[2] = *reinterpret_cast<uint32_t*>(&p2);
                pf[3] = *reinterpret_cast<uint32_t*>(&p3);
            }
            uint32_t bfr2[8][2];
            #pragma unroll
            for (int np = 0; np < 4; np++)
                ldsm4(vb + j * 32 + (uint32_t)(np * 16 * LDV) * 2,
                      bfr2[2 * np][0], bfr2[2 * np][1],
                      bfr2[2 * np + 1][0], bfr2[2 * np + 1][1]);
            #pragma unroll
            for (int ni = 0; ni < 8; ni++)
                mma_f16(oacc[ni], pf, bfr2[ni]);
        }
    }

    l0 += __shfl_xor_sync(0xffffffffu, l0, 1);
    l0 += __shfl_xor_sync(0xffffffffu, l0, 2);
    l1 += __shfl_xor_sync(0xffffffffu, l1, 1);
    l1 += __shfl_xor_sync(0xffffffffu, l1, 2);
    const float inv0 = 1.f / l0, inv1 = 1.f / l1;

    const int row0 = mBase + wid * 16 + gid;
    __half* o0 = ctx + (size_t)(b * SSZ + row0) * DDM + h * 64;
    __half* o1 = o0 + 8 * DDM;
    #pragma unroll
    for (int ni = 0; ni < 8; ni++) {
        const int col = ni * 8 + 2 * tig;
        *reinterpret_cast<__half2*>(o0 + col) =
            __floats2half2_rn(oacc[ni][0] * inv0, oacc[ni][1] * inv0);
        *reinterpret_cast<__half2*>(o1 + col) =
            __floats2half2_rn(oacc[ni][2] * inv1, oacc[ni][3] * inv1);
    }
}

// ---------------- LayerNorm (ddof=1, eps on std, scalar a/b), half out --
__global__ __launch_bounds__(256) void ln_kernel(const float* __restrict__ x,
                                                 __half* __restrict__ y,
                                                 const float* __restrict__ alpha,
                                                 const float* __restrict__ beta)
{
    __shared__ float red[256];
    const int row = blockIdx.x, tid = threadIdx.x;
    const float* xr = x + (size_t)row * DDM;
    __half* yr = y + (size_t)row * DDM;

    float4 v = reinterpret_cast<const float4*>(xr)[tid];
    red[tid] = v.x + v.y + v.z + v.w; __syncthreads();
    for (int o = 128; o > 0; o >>= 1) { if (tid < o) red[tid] += red[tid + o]; __syncthreads(); }
    const float mean = red[0] * (1.0f / DDM);
    __syncthreads();

    float4 d = make_float4(v.x - mean, v.y - mean, v.z - mean, v.w - mean);
    red[tid] = d.x * d.x + d.y * d.y + d.z * d.z + d.w * d.w; __syncthreads();
    for (int o = 128; o > 0; o >>= 1) { if (tid < o) red[tid] += red[tid + o]; __syncthreads(); }
    const float stdv = sqrtf(red[0] * (1.0f / (DDM - 1)));
    const float a = alpha[0], bta = beta[0];
    const float inv = a / (stdv + 1e-6f);

    __half2 o0 = __floats2half2_rn(d.x * inv + bta, d.y * inv + bta);
    __half2 o1 = __floats2half2_rn(d.z * inv + bta, d.w * inv + bta);
    uint2 pk;
    pk.x = *reinterpret_cast<uint32_t*>(&o0);
    pk.y = *reinterpret_cast<uint32_t*>(&o1);
    reinterpret_cast<uint2*>(yr)[tid] = pk;
}

// ---------------- merged weight transpose (all 6 matrices, 1 launch) -----
__global__ void wtrans_all_kernel(const float* __restrict__ wq, const float* __restrict__ wk,
                                  const float* __restrict__ wv, const float* __restrict__ wo,
                                  const float* __restrict__ w1, const float* __restrict__ w2,
                                  __half* __restrict__ wqkvt, __half* __restrict__ wot,
                                  __half* __restrict__ w1t,   __half* __restrict__ w2t)
{
    __shared__ float t[32][33];
    int tIdx = blockIdx.x;
    const float* src; __half* dst; int R, C;
    if (tIdx < 3072) {
        const int m = tIdx >> 10;
        src = (m == 0) ? wq : (m == 1) ? wk : wv;
        dst = wqkvt + (size_t)m * 1024 * 1024;
        R = 1024; C = 1024; tIdx &= 1023;
    } else if (tIdx < 4096) {
        src = wo; dst = wot; R = 1024; C = 1024; tIdx -= 3072;
    } else if (tIdx < 8192) {
        src = w1; dst = w1t; R = 1024; C = 4096; tIdx -= 4096;
    } else {
        src = w2; dst = w2t; R = 4096; C = 1024; tIdx -= 8192;
    }
    const int nCx = C >> 5;
    const int c0 = (tIdx % nCx) * 32, r0 = (tIdx / nCx) * 32;
    const int tx = threadIdx.x, ty = threadIdx.y;
    #pragma unroll
    for (int i = ty; i < 32; i += 8)
        t[i][tx] = src[(size_t)(r0 + i) * C + c0 + tx];
    __syncthreads();
    #pragma unroll
    for (int i = ty; i < 32; i += 8)
        dst[(size_t)(c0 + i) * R + r0 + tx] = __float2half_rn(t[tx][i]);
}

__global__ void vtrans_kernel(const __half* __restrict__ qkv, __half* __restrict__ vt)
{
    __shared__ __half t[32][34];
    const int bh = blockIdx.z, b = bh >> 4, h = bh & 15;
    const int s0 = blockIdx.x * 32, d0 = blockIdx.y * 32;
    const int tx = threadIdx.x, ty = threadIdx.y;
    #pragma unroll
    for (int i = ty; i < 32; i += 8)
        t[i][tx] = qkv[(size_t)(b * SSZ + s0 + i) * QKVLD + 2048 + h * 64 + d0 + tx];
    __syncthreads();
    #pragma unroll
    for (int i = ty; i < 32; i += 8)
        vt[(size_t)bh * 64 * SSZ + (size_t)(d0 + i) * SSZ + s0 + tx] = t[tx][i];
}

__global__ void bcat_kernel(const float* __restrict__ bq, const float* __restrict__ bk,
                            const float* __restrict__ bv, float* __restrict__ dst)
{
    const int i = blockIdx.x * 256 + threadIdx.x;
    if (i < 1024) dst[i] = bq[i];
    else if (i < 2048) dst[i] = bk[i - 1024];
    else dst[i] = bv[i - 2048];
}

// ---------------- launch ----------------
extern "C" void kernel_launch(void* const* d_in, const int* in_sizes, int n_in,
                              void* d_out, int out_size)
{
    const float* x      = (const float*)d_in[0];
    const int*   mask   = (const int*)  d_in[1];
    const float* wq     = (const float*)d_in[2];
    const float* bq     = (const float*)d_in[3];
    const float* wk     = (const float*)d_in[4];
    const float* bk     = (const float*)d_in[5];
    const float* wv     = (const float*)d_in[6];
    const float* bv     = (const float*)d_in[7];
    const float* wo     = (const float*)d_in[8];
    const float* bo     = (const float*)d_in[9];
    const float* w1     = (const float*)d_in[10];
    const float* b1     = (const float*)d_in[11];
    const float* w2     = (const float*)d_in[12];
    const float* b2     = (const float*)d_in[13];
    const float* alpha1 = (const float*)d_in[14];
    const float* beta1  = (const float*)d_in[15];
    const float* alpha2 = (const float*)d_in[16];
    const float* beta2  = (const float*)d_in[17];
    float* out = (float*)d_out;

    cudaFuncSetAttribute((const void*)gemm_mma_kernel<1, 0>, cudaFuncAttributeMaxDynamicSharedMemorySize, G_SMEM);
    cudaFuncSetAttribute((const void*)gemm_mma_kernel<1, 1>, cudaFuncAttributeMaxDynamicSharedMemorySize, G_SMEM);
    cudaFuncSetAttribute((const void*)gemm_mma_kernel<0, 0>, cudaFuncAttributeMaxDynamicSharedMemorySize, G_SMEM);
    cudaFuncSetAttribute((const void*)flash_kernel,          cudaFuncAttributeMaxDynamicSharedMemorySize, FL_SMEM);

    __half *xn, *qkv, *vt, *ctx, *ff, *wqkvt, *wot, *w1t, *w2t;
    float *x1, *bqkv;
    cudaGetSymbolAddress((void**)&xn,    g_xn);
    cudaGetSymbolAddress((void**)&qkv,   g_qkv);
    cudaGetSymbolAddress((void**)&vt,    g_vt);
    cudaGetSymbolAddress((void**)&ctx,   g_ctx);
    cudaGetSymbolAddress((void**)&x1,    g_x1);
    cudaGetSymbolAddress((void**)&ff,    g_ff);
    cudaGetSymbolAddress((void**)&wqkvt, g_wqkvt);
    cudaGetSymbolAddress((void**)&wot,   g_wot);
    cudaGetSymbolAddress((void**)&w1t,   g_w1t);
    cudaGetSymbolAddress((void**)&w2t,   g_w2t);
    cudaGetSymbolAddress((void**)&bqkv,  g_bqkv);

    dim3 tb(32, 8);
    // 0: all weight transposes fp32 -> fp16 K-major
    wtrans_all_kernel<<<12288, tb>>>(wq, wk, wv, wo, w1, w2, wqkvt, wot, w1t, w2t);
    // 1: bias concat
    bcat_kernel<<<12, 256>>>(bq, bk, bv, bqkv);
    // 2: LN1
    ln_kernel<<<ROWS, 256>>>(x, xn, alpha1, beta1);
    // 3: fused QKV projection (half out)
    gemm_mma_kernel<1, 0><<<dim3(24, 32), 256, G_SMEM>>>(xn, DDM, wqkvt, bqkv,
                                                         nullptr, qkv, QKVLD, DDM);
    // 4: V transpose to [bh][d][s]
    vtrans_kernel<<<dim3(32, 2, BHH), tb>>>(qkv, vt);
    // 5: fused flash attention
    flash_kernel<<<dim3(8, BHH), 256, FL_SMEM>>>(qkv, vt, mask, ctx);
    // 6: output projection + residual (float out)
    gemm_mma_kernel<0, 0><<<dim3(8, 32), 256, G_SMEM>>>(ctx, DDM, wot, bo,
                                                        x, x1, DDM, DDM);
    // 7: LN2
    ln_kernel<<<ROWS, 256>>>(x1, xn, alpha2, beta2);
    // 8: FF1 (relu, half out)
    gemm_mma_kernel<1, 1><<<dim3(32, 32), 256, G_SMEM>>>(xn, DDM, w1t, b1,
                                                         nullptr, ff, DFF, DDM);
    // 9: FF2 + residual (float out)
    gemm_mma_kernel<0, 0><<<dim3(8, 32), 256, G_SMEM>>>(ff, DFF, w2t, b2,
                                                        x1, out, DDM, DFF);
}